// round 4
// baseline (speedup 1.0000x reference)
#include <cuda_runtime.h>
#include <cuda_bf16.h>
#include <cuda_fp16.h>
#include <cstdint>

#define B_   2
#define S_   2048
#define E_   1024
#define H_   16
#define D_   64
#define NTOK (B_*S_)

static constexpr long long SSLL = (long long)S_ * S_;                 // 4194304
static constexpr long long SCORES_ELEMS = (long long)B_ * H_ * SSLL;  // 134217728

// ---------------- static scratch ----------------
__device__ __nv_bfloat16 g_xhi[NTOK*E_], g_xlo[NTOK*E_];
__device__ __nv_bfloat16 g_whi[4*E_*E_], g_wlo[4*E_*E_];
__device__ __nv_bfloat16 g_qhi[NTOK*E_], g_qlo[NTOK*E_];
__device__ __nv_bfloat16 g_khi[NTOK*E_], g_klo[NTOK*E_];
__device__ float         g_vf [NTOK*E_];
__device__ __half        g_vt16[NTOK*E_];       // [b][e][k], e=h*64+d
__device__ __half        g_sc16[SCORES_ELEMS];  // scores*log2e/8, fp16 [b,h,q,k]
__device__ __nv_bfloat16 g_chi[NTOK*E_], g_clo[NTOK*E_];

// ---------------- asm helpers ----------------
__device__ __forceinline__ uint32_t smem_u32(const void* p) {
    uint32_t a;
    asm("{ .reg .u64 t; cvta.to.shared.u64 t, %1; cvt.u32.u64 %0, t; }" : "=r"(a) : "l"(p));
    return a;
}
__device__ __forceinline__ void cp16(uint32_t dst, const void* src) {
    asm volatile("cp.async.cg.shared.global [%0], [%1], 16;" :: "r"(dst), "l"(src));
}
__device__ __forceinline__ void cp_commit() { asm volatile("cp.async.commit_group;"); }
__device__ __forceinline__ void cp_wait1()  { asm volatile("cp.async.wait_group 1;"); }
__device__ __forceinline__ void ldsm4(uint32_t* r, uint32_t addr) {
    asm volatile("ldmatrix.sync.aligned.m8n8.x4.shared.b16 {%0,%1,%2,%3}, [%4];"
        : "=r"(r[0]), "=r"(r[1]), "=r"(r[2]), "=r"(r[3]) : "r"(addr));
}
__device__ __forceinline__ void mma_bf16(float* d, const uint32_t* a, const uint32_t* b) {
    asm volatile("mma.sync.aligned.m16n8k16.row.col.f32.bf16.bf16.f32 "
        "{%0,%1,%2,%3}, {%4,%5,%6,%7}, {%8,%9}, {%0,%1,%2,%3};"
        : "+f"(d[0]), "+f"(d[1]), "+f"(d[2]), "+f"(d[3])
        : "r"(a[0]), "r"(a[1]), "r"(a[2]), "r"(a[3]), "r"(b[0]), "r"(b[1]));
}
__device__ __forceinline__ void mma_f16(float* d, const uint32_t* a, const uint32_t* b) {
    asm volatile("mma.sync.aligned.m16n8k16.row.col.f32.f16.f16.f32 "
        "{%0,%1,%2,%3}, {%4,%5,%6,%7}, {%8,%9}, {%0,%1,%2,%3};"
        : "+f"(d[0]), "+f"(d[1]), "+f"(d[2]), "+f"(d[3])
        : "r"(a[0]), "r"(a[1]), "r"(a[2]), "r"(a[3]), "r"(b[0]), "r"(b[1]));
}

// ---------------- utility kernels ----------------
__global__ void split_kernel(const float* __restrict__ src,
                             __nv_bfloat16* __restrict__ hi,
                             __nv_bfloat16* __restrict__ lo, int n) {
    for (int i = blockIdx.x * 256 + threadIdx.x; i < n; i += gridDim.x * 256) {
        float f = src[i];
        __nv_bfloat16 h = __float2bfloat16(f);
        hi[i] = h;
        lo[i] = __float2bfloat16(f - __bfloat162float(h));
    }
}

// v[(b*S+k)*E + e] -> vt16[(b*E+e)*S + k]
__global__ void transpose_f16_kernel(const float* __restrict__ v,
                                     __half* __restrict__ t16) {
    __shared__ float t[32][33];
    int bb = blockIdx.z;
    int k0 = blockIdx.x * 32, e0 = blockIdx.y * 32;
    int tx = threadIdx.x, ty = threadIdx.y;
    for (int i = ty; i < 32; i += 8)
        t[i][tx] = v[((long long)bb * S_ + k0 + i) * E_ + e0 + tx];
    __syncthreads();
    for (int i = ty; i < 32; i += 8) {
        long long o = ((long long)bb * E_ + e0 + i) * S_ + k0 + tx;
        t16[o] = __float2half(t[tx][i]);
    }
}

// ---------------- mma.sync GEMM ----------------
// C = scale*(A @ B^T) + bias; SPLIT: bf16 hi/lo 3-term. Outputs: fp32 / fp16 / split-bf16.
template <int BN, bool SPLIT>
__global__ __launch_bounds__(512)
void gemm_mma(const __nv_bfloat16* __restrict__ Ahi, const __nv_bfloat16* __restrict__ Alo,
              const __nv_bfloat16* __restrict__ Bhi, const __nv_bfloat16* __restrict__ Blo,
              const float* __restrict__ bias,
              float* __restrict__ Cf, __half* __restrict__ C16,
              __nv_bfloat16* __restrict__ Chi, __nv_bfloat16* __restrict__ Clo,
              int lda, int ldb, int ldc, int K, float scale,
              long long aB, long long aH, long long bB, long long bH,
              long long cB, long long cH)
{
    extern __shared__ char smem[];
    constexpr int ASZ = 128 * 80;
    constexpr int BSZ = BN * 80;
    constexpr int OFF_ALO = ASZ;
    constexpr int OFF_BHI = SPLIT ? 2 * ASZ : ASZ;
    constexpr int OFF_BLO = OFF_BHI + BSZ;
    constexpr int STAGE   = OFF_BHI + (SPLIT ? 2 : 1) * BSZ;
    constexpr int NT = BN / 16;

    const int tid  = threadIdx.x;
    const int lane = tid & 31;
    const int wid  = tid >> 5;
    const int wm   = wid & 7;
    const int wn   = wid >> 3;
    const int zb = blockIdx.z >> 4, zh = blockIdx.z & 15;
    const uint32_t sb = smem_u32(smem);

    const __nv_bfloat16* pAhi = Ahi + zb * aB + zh * aH + (long long)blockIdx.y * 128 * lda;
    const __nv_bfloat16* pAlo = SPLIT ? (Alo + zb * aB + zh * aH + (long long)blockIdx.y * 128 * lda) : nullptr;
    const __nv_bfloat16* pBhi = Bhi + zb * bB + zh * bH + (long long)blockIdx.x * BN * ldb;
    const __nv_bfloat16* pBlo = SPLIT ? (Blo + zb * bB + zh * bH + (long long)blockIdx.x * BN * ldb) : nullptr;

    const int arow = tid >> 2, ac = tid & 3;
    const int brow = tid >> 2, bc = tid & 3;

    auto load_stage = [&](int kb, int stg) {
        uint32_t s0 = sb + stg * STAGE;
        {
            long long g = (long long)arow * lda + kb * 32 + ac * 8;
            uint32_t d = s0 + arow * 80 + ac * 16;
            cp16(d, pAhi + g);
            if (SPLIT) cp16(d + OFF_ALO, pAlo + g);
        }
        if (BN == 128 || tid < BN * 4) {
            long long g = (long long)brow * ldb + kb * 32 + bc * 8;
            uint32_t d = s0 + OFF_BHI + brow * 80 + bc * 16;
            cp16(d, pBhi + g);
            if (SPLIT) cp16(d + (OFF_BLO - OFF_BHI), pBlo + g);
        }
    };

    const int KI = K >> 5;
    load_stage(0, 0); cp_commit();
    load_stage(1, 1); cp_commit();

    float acc[NT][4];
#pragma unroll
    for (int t = 0; t < NT; t++)
#pragma unroll
        for (int i = 0; i < 4; i++) acc[t][i] = 0.f;

    const int a_r = wm * 16 + (lane & 15);
    const int a_c = (lane >> 4) * 16;
    const int b_r = wn * (BN / 2) + (lane & 7) + ((lane >> 4) & 1) * 8;
    const int b_c = ((lane >> 3) & 1) * 16;

    for (int kb = 0; kb < KI; kb++) {
        cp_wait1();
        __syncthreads();
        const uint32_t s0 = sb + (kb & 1) * STAGE;
#pragma unroll
        for (int ks = 0; ks < 2; ks++) {
            const uint32_t koff = ks * 32;
            uint32_t ah[4], bh[NT * 2];
            ldsm4(ah, s0 + a_r * 80 + a_c + koff);
#pragma unroll
            for (int t2 = 0; t2 < NT / 2; t2++) {
                uint32_t r4[4];
                ldsm4(r4, s0 + OFF_BHI + (b_r + t2 * 16) * 80 + b_c + koff);
                bh[t2*4+0] = r4[0]; bh[t2*4+1] = r4[1]; bh[t2*4+2] = r4[2]; bh[t2*4+3] = r4[3];
            }
            if (SPLIT) {
#pragma unroll
                for (int t = 0; t < NT; t++) mma_bf16(acc[t], ah, &bh[t * 2]);
                uint32_t bl[NT * 2];
#pragma unroll
                for (int t2 = 0; t2 < NT / 2; t2++) {
                    uint32_t r4[4];
                    ldsm4(r4, s0 + OFF_BLO + (b_r + t2 * 16) * 80 + b_c + koff);
                    bl[t2*4+0] = r4[0]; bl[t2*4+1] = r4[1]; bl[t2*4+2] = r4[2]; bl[t2*4+3] = r4[3];
                }
#pragma unroll
                for (int t = 0; t < NT; t++) mma_bf16(acc[t], ah, &bl[t * 2]);
                uint32_t al[4];
                ldsm4(al, s0 + OFF_ALO + a_r * 80 + a_c + koff);
#pragma unroll
                for (int t = 0; t < NT; t++) mma_bf16(acc[t], al, &bh[t * 2]);
            } else {
#pragma unroll
                for (int t = 0; t < NT; t++) mma_f16(acc[t], ah, &bh[t * 2]);
            }
        }
        __syncthreads();
        if (kb + 2 < KI) load_stage(kb + 2, kb & 1);
        cp_commit();
    }

    const int mrow = blockIdx.y * 128 + wm * 16 + (lane >> 2);
    const int ncol0 = blockIdx.x * BN + wn * (BN / 2);
    const long long cb = zb * cB + zh * cH;
#pragma unroll
    for (int t = 0; t < NT; t++) {
        const int col = ncol0 + t * 8 + (lane & 3) * 2;
        float v0 = acc[t][0] * scale, v1 = acc[t][1] * scale;
        float v2 = acc[t][2] * scale, v3 = acc[t][3] * scale;
        if (bias) {
            float b0 = __ldg(&bias[col]), b1 = __ldg(&bias[col + 1]);
            v0 += b0; v1 += b1; v2 += b0; v3 += b1;
        }
        if (Cf) {
            *(float2*)(Cf + cb + (long long)mrow * ldc + col)       = make_float2(v0, v1);
            *(float2*)(Cf + cb + (long long)(mrow + 8) * ldc + col) = make_float2(v2, v3);
        } else if (C16) {
            __half2 p0; p0.x = __float2half(v0); p0.y = __float2half(v1);
            __half2 p1; p1.x = __float2half(v2); p1.y = __float2half(v3);
            *(__half2*)(C16 + cb + (long long)mrow * ldc + col)       = p0;
            *(__half2*)(C16 + cb + (long long)(mrow + 8) * ldc + col) = p1;
        } else {
            __nv_bfloat16 h0 = __float2bfloat16(v0), h1 = __float2bfloat16(v1);
            __nv_bfloat16 h2 = __float2bfloat16(v2), h3 = __float2bfloat16(v3);
            __nv_bfloat162 hp0; hp0.x = h0; hp0.y = h1;
            __nv_bfloat162 hp1; hp1.x = h2; hp1.y = h3;
            __nv_bfloat162 lp0; lp0.x = __float2bfloat16(v0 - __bfloat162float(h0));
                                lp0.y = __float2bfloat16(v1 - __bfloat162float(h1));
            __nv_bfloat162 lp1; lp1.x = __float2bfloat16(v2 - __bfloat162float(h2));
                                lp1.y = __float2bfloat16(v3 - __bfloat162float(h3));
            *(__nv_bfloat162*)(Chi + cb + (long long)mrow * ldc + col)       = hp0;
            *(__nv_bfloat162*)(Chi + cb + (long long)(mrow + 8) * ldc + col) = hp1;
            *(__nv_bfloat162*)(Clo + cb + (long long)mrow * ldc + col)       = lp0;
            *(__nv_bfloat162*)(Clo + cb + (long long)(mrow + 8) * ldc + col) = lp1;
        }
    }
}

// ---------------- fused heads-softmax + PV ----------------
// Block: 32 queries x all 16 heads (warp = head), 512 threads.
// Loops 128 k-tiles of 16. sc16 holds scores*log2e (exp2 domain).
// ctx written split-bf16 to chi/clo at [b][q][h*64+d].
#define AQT 32
#define AKT 16
#define SC_ST  24576          // 16h*32q rows * 48B
#define AV_OFF (2*SC_ST)      // 49152
#define AV_ST  49152          // 16h*64d rows * 48B
#define ATT_SMEM (AV_OFF + 2*AV_ST)   // 147456

__global__ __launch_bounds__(512)
void attn_fused(const __half* __restrict__ sc16, const __half* __restrict__ vt16,
                __nv_bfloat16* __restrict__ chi, __nv_bfloat16* __restrict__ clo)
{
    extern __shared__ char smem[];
    const int tid = threadIdx.x, lane = tid & 31, wid = tid >> 5;  // wid = head
    const int b = blockIdx.y;
    const int q0 = blockIdx.x * AQT;
    const uint32_t sb = smem_u32(smem);

    // staging: sc rows r in [0,512): h=r>>5, q=r&31; 2 x 16B chunks per row
    auto load_sc = [&](int kt, int stg) {
        const uint32_t d0 = sb + stg * SC_ST;
#pragma unroll
        for (int p = 0; p < 2; p++) {
            int idx = tid + p * 512;          // 0..1023
            int r = idx >> 1, c = idx & 1;
            int h = r >> 5, q = r & 31;
            long long g = (((long long)(b * H_ + h)) * S_ + q0 + q) * S_ + kt * AKT + c * 8;
            cp16(d0 + r * 48 + c * 16, sc16 + g);
        }
    };
    // v rows r in [0,1024): h=r>>6, d=r&63
    auto load_v = [&](int kt, int stg) {
        const uint32_t d0 = sb + AV_OFF + stg * AV_ST;
#pragma unroll
        for (int p = 0; p < 4; p++) {
            int idx = tid + p * 512;          // 0..2047
            int r = idx >> 1, c = idx & 1;
            long long g = ((long long)b * E_ + r) * S_ + kt * AKT + c * 8;
            cp16(d0 + r * 48 + c * 16, vt16 + g);
        }
    };

    load_sc(0, 0); load_v(0, 0); cp_commit();
    load_sc(1, 1); load_v(1, 1); cp_commit();

    float acc[2][8][4];
#pragma unroll
    for (int m = 0; m < 2; m++)
#pragma unroll
        for (int n = 0; n < 8; n++)
#pragma unroll
            for (int i = 0; i < 4; i++) acc[m][n][i] = 0.f;

    const int sq = tid >> 4, sk = tid & 15;   // softmax position

    for (int kt = 0; kt < S_ / AKT; kt++) {
        cp_wait1();
        __syncthreads();
        const int stg = kt & 1;
        const uint32_t scb = sb + stg * SC_ST;
        const uint32_t vb  = sb + AV_OFF + stg * AV_ST;

        // heads-softmax at (sq, sk): exp2 then normalize, in place (fp16)
        {
            const uint32_t a0 = scb + sq * 48 + sk * 2;
            float sum = 0.f;
#pragma unroll
            for (int h = 0; h < H_; h++) {
                uint16_t raw;
                asm volatile("ld.shared.u16 %0, [%1];" : "=h"(raw) : "r"(a0 + h * 1536));
                float e = exp2f(__half2float(__ushort_as_half(raw)));
                uint16_t er = __half_as_ushort(__float2half(e));
                asm volatile("st.shared.u16 [%0], %1;" :: "r"(a0 + h * 1536), "h"(er));
                sum += e;
            }
            float inv = 1.f / sum;
#pragma unroll
            for (int h = 0; h < H_; h++) {
                uint16_t raw;
                asm volatile("ld.shared.u16 %0, [%1];" : "=h"(raw) : "r"(a0 + h * 1536));
                float p = __half2float(__ushort_as_half(raw)) * inv;
                uint16_t pr = __half_as_ushort(__float2half(p));
                asm volatile("st.shared.u16 [%0], %1;" :: "r"(a0 + h * 1536), "h"(pr));
            }
        }
        __syncthreads();

        // PV MMA: warp = head
        const uint32_t pa = scb + wid * 1536;        // probs [32q][48B rows]
        const uint32_t va = vb + wid * 3072;         // v [64d][48B rows]
        uint32_t af0[4], af1[4];
        ldsm4(af0, pa + (lane & 15) * 48 + (lane >> 4) * 16);
        ldsm4(af1, pa + (16 + (lane & 15)) * 48 + (lane >> 4) * 16);
#pragma unroll
        for (int nt2 = 0; nt2 < 4; nt2++) {
            uint32_t bf[4];
            ldsm4(bf, va + (nt2 * 16 + (lane & 7) + ((lane >> 4) & 1) * 8) * 48
                       + ((lane >> 3) & 1) * 16);
            mma_f16(acc[0][nt2 * 2],     af0, &bf[0]);
            mma_f16(acc[0][nt2 * 2 + 1], af0, &bf[2]);
            mma_f16(acc[1][nt2 * 2],     af1, &bf[0]);
            mma_f16(acc[1][nt2 * 2 + 1], af1, &bf[2]);
        }
        __syncthreads();
        if (kt + 2 < S_ / AKT) { load_sc(kt + 2, stg); load_v(kt + 2, stg); }
        cp_commit();
    }

    // epilogue: ctx[b][q][h*64+d] split-bf16
    const int col0 = wid * 64 + (lane & 3) * 2;
#pragma unroll
    for (int m = 0; m < 2; m++) {
        const int row = q0 + m * 16 + (lane >> 2);
#pragma unroll
        for (int n = 0; n < 8; n++) {
            const int col = col0 + n * 8;
            float v0 = acc[m][n][0], v1 = acc[m][n][1];
            float v2 = acc[m][n][2], v3 = acc[m][n][3];
            __nv_bfloat16 h0 = __float2bfloat16(v0), h1 = __float2bfloat16(v1);
            __nv_bfloat16 h2 = __float2bfloat16(v2), h3 = __float2bfloat16(v3);
            __nv_bfloat162 hp0; hp0.x = h0; hp0.y = h1;
            __nv_bfloat162 hp1; hp1.x = h2; hp1.y = h3;
            __nv_bfloat162 lp0; lp0.x = __float2bfloat16(v0 - __bfloat162float(h0));
                                lp0.y = __float2bfloat16(v1 - __bfloat162float(h1));
            __nv_bfloat162 lp1; lp1.x = __float2bfloat16(v2 - __bfloat162float(h2));
                                lp1.y = __float2bfloat16(v3 - __bfloat162float(h3));
            long long o0 = ((long long)(b * S_ + row)) * E_ + col;
            long long o1 = ((long long)(b * S_ + row + 8)) * E_ + col;
            *(__nv_bfloat162*)(chi + o0) = hp0;
            *(__nv_bfloat162*)(chi + o1) = hp1;
            *(__nv_bfloat162*)(clo + o0) = lp0;
            *(__nv_bfloat162*)(clo + o1) = lp1;
        }
    }
}

// ---------------- launch ----------------
extern "C" void kernel_launch(void* const* d_in, const int* in_sizes, int n_in,
                              void* d_out, int out_size)
{
    const float* x  = (const float*)d_in[0];
    const float* Wq = (const float*)d_in[1];
    const float* bq = (const float*)d_in[2];
    const float* Wk = (const float*)d_in[3];
    const float* bk = (const float*)d_in[4];
    const float* Wv = (const float*)d_in[5];
    const float* bv = (const float*)d_in[6];
    const float* Wo = (const float*)d_in[7];
    const float* bo = (const float*)d_in[8];
    float* out = (float*)d_out;

    __nv_bfloat16 *xhi, *xlo, *whi, *wlo, *qhi, *qlo, *khi, *klo, *chi, *clo;
    __half *vt16, *sc16;
    float *vf;
    cudaGetSymbolAddress((void**)&xhi, g_xhi);  cudaGetSymbolAddress((void**)&xlo, g_xlo);
    cudaGetSymbolAddress((void**)&whi, g_whi);  cudaGetSymbolAddress((void**)&wlo, g_wlo);
    cudaGetSymbolAddress((void**)&qhi, g_qhi);  cudaGetSymbolAddress((void**)&qlo, g_qlo);
    cudaGetSymbolAddress((void**)&khi, g_khi);  cudaGetSymbolAddress((void**)&klo, g_klo);
    cudaGetSymbolAddress((void**)&vf,  g_vf);
    cudaGetSymbolAddress((void**)&vt16, g_vt16);
    cudaGetSymbolAddress((void**)&sc16, g_sc16);
    cudaGetSymbolAddress((void**)&chi, g_chi);  cudaGetSymbolAddress((void**)&clo, g_clo);

    constexpr int SMEM_SPLIT = 2 * (2 * 128 * 80 + 2 * 128 * 80);  // 81920
    cudaFuncSetAttribute(gemm_mma<128, true>, cudaFuncAttributeMaxDynamicSharedMemorySize, SMEM_SPLIT);
    cudaFuncSetAttribute(attn_fused, cudaFuncAttributeMaxDynamicSharedMemorySize, ATT_SMEM);

    const int EE = E_ * E_;

    // 1) split fp32 -> bf16 hi/lo
    split_kernel<<<2048, 256>>>(x,  xhi, xlo, NTOK * E_);
    split_kernel<<<1024, 256>>>(Wq, whi + 0 * EE, wlo + 0 * EE, EE);
    split_kernel<<<1024, 256>>>(Wk, whi + 1 * EE, wlo + 1 * EE, EE);
    split_kernel<<<1024, 256>>>(Wv, whi + 2 * EE, wlo + 2 * EE, EE);
    split_kernel<<<1024, 256>>>(Wo, whi + 3 * EE, wlo + 3 * EE, EE);

    // 2) projections
    dim3 gp(E_ / 128, NTOK / 128, 1);  // (8, 32)
    gemm_mma<128, true><<<gp, 512, SMEM_SPLIT>>>(xhi, xlo, whi + 0 * EE, wlo + 0 * EE, bq,
        nullptr, nullptr, qhi, qlo, E_, E_, E_, E_, 1.f, 0, 0, 0, 0, 0, 0);
    gemm_mma<128, true><<<gp, 512, SMEM_SPLIT>>>(xhi, xlo, whi + 1 * EE, wlo + 1 * EE, bk,
        nullptr, nullptr, khi, klo, E_, E_, E_, E_, 1.f, 0, 0, 0, 0, 0, 0);
    gemm_mma<128, true><<<gp, 512, SMEM_SPLIT>>>(xhi, xlo, whi + 2 * EE, wlo + 2 * EE, bv,
        vf, nullptr, nullptr, nullptr, E_, E_, E_, E_, 1.f, 0, 0, 0, 0, 0, 0);

    // 3) transpose v -> vt16[b][e][k]
    transpose_f16_kernel<<<dim3(S_ / 32, E_ / 32, B_), dim3(32, 8)>>>(vf, vt16);

    // 4) scores[b,h,q,k] = (q.k) * (log2e/8), fp16 out, batched z = b*16+h, K=64
    gemm_mma<128, true><<<dim3(S_ / 128, S_ / 128, B_ * H_), 512, SMEM_SPLIT>>>(
        qhi, qlo, khi, klo, nullptr, nullptr, sc16, nullptr, nullptr,
        E_, E_, S_, D_, 0.125f * 1.4426950408889634f,
        (long long)S_ * E_, 64LL, (long long)S_ * E_, 64LL,
        (long long)H_ * SSLL, SSLL);

    // 5) fused heads-softmax + PV -> ctx split-bf16
    attn_fused<<<dim3(S_ / AQT, B_), 512, ATT_SMEM>>>(sc16, vt16, chi, clo);

    // 6) output projection -> d_out (fp32)
    gemm_mma<128, true><<<gp, 512, SMEM_SPLIT>>>(chi, clo, whi + 3 * EE, wlo + 3 * EE, bo,
        out, nullptr, nullptr, nullptr, E_, E_, E_, E_, 1.f, 0, 0, 0, 0, 0, 0);
}

// round 5
// speedup vs baseline: 1.2397x; 1.2397x over previous
#include <cuda_runtime.h>
#include <cuda_bf16.h>
#include <cuda_fp16.h>
#include <cstdint>

#define B_   2
#define S_   2048
#define E_   1024
#define H_   16
#define D_   64
#define NTOK (B_*S_)

static constexpr long long SSLL = (long long)S_ * S_;                 // 4194304
static constexpr long long SCORES_ELEMS = (long long)B_ * H_ * SSLL;  // 134217728

// ---------------- static scratch ----------------
__device__ __nv_bfloat16 g_xhi[NTOK*E_], g_xlo[NTOK*E_];
__device__ __nv_bfloat16 g_whi[4*E_*E_], g_wlo[4*E_*E_];
__device__ __half        g_q16[NTOK*E_], g_k16[NTOK*E_];
__device__ __half        g_v16[NTOK*E_];        // [b*S+k][e]
__device__ __half        g_vt16[NTOK*E_];       // [b][e][k], e=h*64+d
__device__ __half        g_sc16[SCORES_ELEMS];  // scores*log2e/8 fp16; softmax in-place
__device__ __nv_bfloat16 g_chi[NTOK*E_], g_clo[NTOK*E_];

// ---------------- asm helpers ----------------
__device__ __forceinline__ uint32_t smem_u32(const void* p) {
    uint32_t a;
    asm("{ .reg .u64 t; cvta.to.shared.u64 t, %1; cvt.u32.u64 %0, t; }" : "=r"(a) : "l"(p));
    return a;
}
__device__ __forceinline__ void cp16(uint32_t dst, const void* src) {
    asm volatile("cp.async.cg.shared.global [%0], [%1], 16;" :: "r"(dst), "l"(src));
}
__device__ __forceinline__ void cp_commit() { asm volatile("cp.async.commit_group;"); }
__device__ __forceinline__ void cp_wait1()  { asm volatile("cp.async.wait_group 1;"); }
__device__ __forceinline__ void ldsm4(uint32_t* r, uint32_t addr) {
    asm volatile("ldmatrix.sync.aligned.m8n8.x4.shared.b16 {%0,%1,%2,%3}, [%4];"
        : "=r"(r[0]), "=r"(r[1]), "=r"(r[2]), "=r"(r[3]) : "r"(addr));
}
__device__ __forceinline__ void mma_bf16(float* d, const uint32_t* a, const uint32_t* b) {
    asm volatile("mma.sync.aligned.m16n8k16.row.col.f32.bf16.bf16.f32 "
        "{%0,%1,%2,%3}, {%4,%5,%6,%7}, {%8,%9}, {%0,%1,%2,%3};"
        : "+f"(d[0]), "+f"(d[1]), "+f"(d[2]), "+f"(d[3])
        : "r"(a[0]), "r"(a[1]), "r"(a[2]), "r"(a[3]), "r"(b[0]), "r"(b[1]));
}
__device__ __forceinline__ void mma_f16(float* d, const uint32_t* a, const uint32_t* b) {
    asm volatile("mma.sync.aligned.m16n8k16.row.col.f32.f16.f16.f32 "
        "{%0,%1,%2,%3}, {%4,%5,%6,%7}, {%8,%9}, {%0,%1,%2,%3};"
        : "+f"(d[0]), "+f"(d[1]), "+f"(d[2]), "+f"(d[3])
        : "r"(a[0]), "r"(a[1]), "r"(a[2]), "r"(a[3]), "r"(b[0]), "r"(b[1]));
}

// ---------------- utility kernels ----------------
__global__ void split_kernel(const float* __restrict__ src,
                             __nv_bfloat16* __restrict__ hi,
                             __nv_bfloat16* __restrict__ lo, int n) {
    for (int i = blockIdx.x * 256 + threadIdx.x; i < n; i += gridDim.x * 256) {
        float f = src[i];
        __nv_bfloat16 h = __float2bfloat16(f);
        hi[i] = h;
        lo[i] = __float2bfloat16(f - __bfloat162float(h));
    }
}

// v16[(b*S+k)*E + e] -> vt16[(b*E+e)*S + k]
__global__ void transpose_f16f16_kernel(const __half* __restrict__ v,
                                        __half* __restrict__ t16) {
    __shared__ __half t[32][40];
    int bb = blockIdx.z;
    int k0 = blockIdx.x * 32, e0 = blockIdx.y * 32;
    int tx = threadIdx.x, ty = threadIdx.y;
    for (int i = ty; i < 32; i += 8)
        t[i][tx] = v[((long long)bb * S_ + k0 + i) * E_ + e0 + tx];
    __syncthreads();
    for (int i = ty; i < 32; i += 8) {
        long long o = ((long long)bb * E_ + e0 + i) * S_ + k0 + tx;
        t16[o] = t[tx][i];
    }
}

// softmax over 16 heads per (b,q,k), half2 vectorized (2 k per thread), in place.
// input is scores*log2e/8 (exp2 domain).
__global__ void softmax_heads16_kernel(__half* __restrict__ sc) {
    long long p = (long long)blockIdx.x * 256 + threadIdx.x;  // pair idx over B*S*S/2
    int k2 = (int)(p & (S_ / 2 - 1));
    int q  = (int)((p >> 10) & (S_ - 1));
    int b  = (int)(p >> 21);
    long long base = (((long long)b * H_) * S_ + q) * S_ + k2 * 2;
    float e0[H_], e1[H_];
    float s0 = 0.f, s1 = 0.f;
#pragma unroll
    for (int h = 0; h < H_; h++) {
        __half2 v = *(const __half2*)(sc + base + (long long)h * SSLL);
        float2 f = __half22float2(v);
        e0[h] = exp2f(f.x); e1[h] = exp2f(f.y);
        s0 += e0[h]; s1 += e1[h];
    }
    float i0 = 1.f / s0, i1 = 1.f / s1;
#pragma unroll
    for (int h = 0; h < H_; h++) {
        __half2 r; r.x = __float2half(e0[h] * i0); r.y = __float2half(e1[h] * i1);
        *(__half2*)(sc + base + (long long)h * SSLL) = r;
    }
}

// ---------------- mma.sync GEMM ----------------
// C = scale*(A @ B^T) + bias; SPLIT: bf16 hi/lo 3-term; else fp16 single.
// Outputs: fp32 (Cf) / fp16 (C16) / split-bf16 (Chi/Clo).
template <int BN, bool SPLIT>
__global__ __launch_bounds__(512)
void gemm_mma(const __nv_bfloat16* __restrict__ Ahi, const __nv_bfloat16* __restrict__ Alo,
              const __nv_bfloat16* __restrict__ Bhi, const __nv_bfloat16* __restrict__ Blo,
              const float* __restrict__ bias,
              float* __restrict__ Cf, __half* __restrict__ C16,
              __nv_bfloat16* __restrict__ Chi, __nv_bfloat16* __restrict__ Clo,
              int lda, int ldb, int ldc, int K, float scale,
              long long aB, long long aH, long long bB, long long bH,
              long long cB, long long cH)
{
    extern __shared__ char smem[];
    constexpr int ASZ = 128 * 80;
    constexpr int BSZ = BN * 80;
    constexpr int OFF_ALO = ASZ;
    constexpr int OFF_BHI = SPLIT ? 2 * ASZ : ASZ;
    constexpr int OFF_BLO = OFF_BHI + BSZ;
    constexpr int STAGE   = OFF_BHI + (SPLIT ? 2 : 1) * BSZ;
    constexpr int NT = BN / 16;

    const int tid  = threadIdx.x;
    const int lane = tid & 31;
    const int wid  = tid >> 5;
    const int wm   = wid & 7;
    const int wn   = wid >> 3;
    const int zb = blockIdx.z >> 4, zh = blockIdx.z & 15;
    const uint32_t sb = smem_u32(smem);

    const __nv_bfloat16* pAhi = Ahi + zb * aB + zh * aH + (long long)blockIdx.y * 128 * lda;
    const __nv_bfloat16* pAlo = SPLIT ? (Alo + zb * aB + zh * aH + (long long)blockIdx.y * 128 * lda) : nullptr;
    const __nv_bfloat16* pBhi = Bhi + zb * bB + zh * bH + (long long)blockIdx.x * BN * ldb;
    const __nv_bfloat16* pBlo = SPLIT ? (Blo + zb * bB + zh * bH + (long long)blockIdx.x * BN * ldb) : nullptr;

    const int arow = tid >> 2, ac = tid & 3;
    const int brow = tid >> 2, bc = tid & 3;

    auto load_stage = [&](int kb, int stg) {
        uint32_t s0 = sb + stg * STAGE;
        {
            long long g = (long long)arow * lda + kb * 32 + ac * 8;
            uint32_t d = s0 + arow * 80 + ac * 16;
            cp16(d, pAhi + g);
            if (SPLIT) cp16(d + OFF_ALO, pAlo + g);
        }
        if (BN == 128 || tid < BN * 4) {
            long long g = (long long)brow * ldb + kb * 32 + bc * 8;
            uint32_t d = s0 + OFF_BHI + brow * 80 + bc * 16;
            cp16(d, pBhi + g);
            if (SPLIT) cp16(d + (OFF_BLO - OFF_BHI), pBlo + g);
        }
    };

    const int KI = K >> 5;
    load_stage(0, 0); cp_commit();
    load_stage(1, 1); cp_commit();

    float acc[NT][4];
#pragma unroll
    for (int t = 0; t < NT; t++)
#pragma unroll
        for (int i = 0; i < 4; i++) acc[t][i] = 0.f;

    const int a_r = wm * 16 + (lane & 15);
    const int a_c = (lane >> 4) * 16;
    const int b_r = wn * (BN / 2) + (lane & 7) + ((lane >> 4) & 1) * 8;
    const int b_c = ((lane >> 3) & 1) * 16;

    for (int kb = 0; kb < KI; kb++) {
        cp_wait1();
        __syncthreads();
        const uint32_t s0 = sb + (kb & 1) * STAGE;
#pragma unroll
        for (int ks = 0; ks < 2; ks++) {
            const uint32_t koff = ks * 32;
            uint32_t ah[4], bh[NT * 2];
            ldsm4(ah, s0 + a_r * 80 + a_c + koff);
#pragma unroll
            for (int t2 = 0; t2 < NT / 2; t2++) {
                uint32_t r4[4];
                ldsm4(r4, s0 + OFF_BHI + (b_r + t2 * 16) * 80 + b_c + koff);
                bh[t2*4+0] = r4[0]; bh[t2*4+1] = r4[1]; bh[t2*4+2] = r4[2]; bh[t2*4+3] = r4[3];
            }
            if (SPLIT) {
#pragma unroll
                for (int t = 0; t < NT; t++) mma_bf16(acc[t], ah, &bh[t * 2]);
                uint32_t bl[NT * 2];
#pragma unroll
                for (int t2 = 0; t2 < NT / 2; t2++) {
                    uint32_t r4[4];
                    ldsm4(r4, s0 + OFF_BLO + (b_r + t2 * 16) * 80 + b_c + koff);
                    bl[t2*4+0] = r4[0]; bl[t2*4+1] = r4[1]; bl[t2*4+2] = r4[2]; bl[t2*4+3] = r4[3];
                }
#pragma unroll
                for (int t = 0; t < NT; t++) mma_bf16(acc[t], ah, &bl[t * 2]);
                uint32_t al[4];
                ldsm4(al, s0 + OFF_ALO + a_r * 80 + a_c + koff);
#pragma unroll
                for (int t = 0; t < NT; t++) mma_bf16(acc[t], al, &bh[t * 2]);
            } else {
#pragma unroll
                for (int t = 0; t < NT; t++) mma_f16(acc[t], ah, &bh[t * 2]);
            }
        }
        __syncthreads();
        if (kb + 2 < KI) load_stage(kb + 2, kb & 1);
        cp_commit();
    }

    const int mrow = blockIdx.y * 128 + wm * 16 + (lane >> 2);
    const int ncol0 = blockIdx.x * BN + wn * (BN / 2);
    const long long cb = zb * cB + zh * cH;
#pragma unroll
    for (int t = 0; t < NT; t++) {
        const int col = ncol0 + t * 8 + (lane & 3) * 2;
        float v0 = acc[t][0] * scale, v1 = acc[t][1] * scale;
        float v2 = acc[t][2] * scale, v3 = acc[t][3] * scale;
        if (bias) {
            float b0 = __ldg(&bias[col]), b1 = __ldg(&bias[col + 1]);
            v0 += b0; v1 += b1; v2 += b0; v3 += b1;
        }
        if (Cf) {
            *(float2*)(Cf + cb + (long long)mrow * ldc + col)       = make_float2(v0, v1);
            *(float2*)(Cf + cb + (long long)(mrow + 8) * ldc + col) = make_float2(v2, v3);
        } else if (C16) {
            __half2 p0; p0.x = __float2half(v0); p0.y = __float2half(v1);
            __half2 p1; p1.x = __float2half(v2); p1.y = __float2half(v3);
            *(__half2*)(C16 + cb + (long long)mrow * ldc + col)       = p0;
            *(__half2*)(C16 + cb + (long long)(mrow + 8) * ldc + col) = p1;
        } else {
            __nv_bfloat16 h0 = __float2bfloat16(v0), h1 = __float2bfloat16(v1);
            __nv_bfloat16 h2 = __float2bfloat16(v2), h3 = __float2bfloat16(v3);
            __nv_bfloat162 hp0; hp0.x = h0; hp0.y = h1;
            __nv_bfloat162 hp1; hp1.x = h2; hp1.y = h3;
            __nv_bfloat162 lp0; lp0.x = __float2bfloat16(v0 - __bfloat162float(h0));
                                lp0.y = __float2bfloat16(v1 - __bfloat162float(h1));
            __nv_bfloat162 lp1; lp1.x = __float2bfloat16(v2 - __bfloat162float(h2));
                                lp1.y = __float2bfloat16(v3 - __bfloat162float(h3));
            *(__nv_bfloat162*)(Chi + cb + (long long)mrow * ldc + col)       = hp0;
            *(__nv_bfloat162*)(Chi + cb + (long long)(mrow + 8) * ldc + col) = hp1;
            *(__nv_bfloat162*)(Clo + cb + (long long)mrow * ldc + col)       = lp0;
            *(__nv_bfloat162*)(Clo + cb + (long long)(mrow + 8) * ldc + col) = lp1;
        }
    }
}

// ---------------- launch ----------------
extern "C" void kernel_launch(void* const* d_in, const int* in_sizes, int n_in,
                              void* d_out, int out_size)
{
    const float* x  = (const float*)d_in[0];
    const float* Wq = (const float*)d_in[1];
    const float* bq = (const float*)d_in[2];
    const float* Wk = (const float*)d_in[3];
    const float* bk = (const float*)d_in[4];
    const float* Wv = (const float*)d_in[5];
    const float* bv = (const float*)d_in[6];
    const float* Wo = (const float*)d_in[7];
    const float* bo = (const float*)d_in[8];
    float* out = (float*)d_out;

    __nv_bfloat16 *xhi, *xlo, *whi, *wlo, *chi, *clo;
    __half *q16, *k16, *v16, *vt16, *sc16;
    cudaGetSymbolAddress((void**)&xhi, g_xhi);  cudaGetSymbolAddress((void**)&xlo, g_xlo);
    cudaGetSymbolAddress((void**)&whi, g_whi);  cudaGetSymbolAddress((void**)&wlo, g_wlo);
    cudaGetSymbolAddress((void**)&q16, g_q16);  cudaGetSymbolAddress((void**)&k16, g_k16);
    cudaGetSymbolAddress((void**)&v16, g_v16);
    cudaGetSymbolAddress((void**)&vt16, g_vt16);
    cudaGetSymbolAddress((void**)&sc16, g_sc16);
    cudaGetSymbolAddress((void**)&chi, g_chi);  cudaGetSymbolAddress((void**)&clo, g_clo);

    constexpr int SMEM_SPLIT = 2 * (2 * 128 * 80 + 2 * 128 * 80);  // 81920
    constexpr int SMEM_F16_128 = 2 * (128 * 80 + 128 * 80);        // 40960
    constexpr int SMEM_F16_64  = 2 * (128 * 80 + 64 * 80);         // 30720
    cudaFuncSetAttribute(gemm_mma<128, true>, cudaFuncAttributeMaxDynamicSharedMemorySize, SMEM_SPLIT);

    const int EE = E_ * E_;

    // 1) split fp32 -> bf16 hi/lo for x and weights
    split_kernel<<<2048, 256>>>(x,  xhi, xlo, NTOK * E_);
    split_kernel<<<1024, 256>>>(Wq, whi + 0 * EE, wlo + 0 * EE, EE);
    split_kernel<<<1024, 256>>>(Wk, whi + 1 * EE, wlo + 1 * EE, EE);
    split_kernel<<<1024, 256>>>(Wv, whi + 2 * EE, wlo + 2 * EE, EE);
    split_kernel<<<1024, 256>>>(Wo, whi + 3 * EE, wlo + 3 * EE, EE);

    // 2) projections: q,k,v all emit fp16
    dim3 gp(E_ / 128, NTOK / 128, 1);  // (8, 32)
    gemm_mma<128, true><<<gp, 512, SMEM_SPLIT>>>(xhi, xlo, whi + 0 * EE, wlo + 0 * EE, bq,
        nullptr, q16, nullptr, nullptr, E_, E_, E_, E_, 1.f, 0, 0, 0, 0, 0, 0);
    gemm_mma<128, true><<<gp, 512, SMEM_SPLIT>>>(xhi, xlo, whi + 1 * EE, wlo + 1 * EE, bk,
        nullptr, k16, nullptr, nullptr, E_, E_, E_, E_, 1.f, 0, 0, 0, 0, 0, 0);
    gemm_mma<128, true><<<gp, 512, SMEM_SPLIT>>>(xhi, xlo, whi + 2 * EE, wlo + 2 * EE, bv,
        nullptr, v16, nullptr, nullptr, E_, E_, E_, E_, 1.f, 0, 0, 0, 0, 0, 0);

    // 3) transpose v -> vt16[b][e][k]
    transpose_f16f16_kernel<<<dim3(S_ / 32, E_ / 32, B_), dim3(32, 8)>>>(v16, vt16);

    // 4) scores[b,h,q,k] = (q.k)*(log2e/8), fp16 single-term, fp16 out
    gemm_mma<128, false><<<dim3(S_ / 128, S_ / 128, B_ * H_), 512, SMEM_F16_128>>>(
        (const __nv_bfloat16*)q16, nullptr, (const __nv_bfloat16*)k16, nullptr,
        nullptr, nullptr, sc16, nullptr, nullptr,
        E_, E_, S_, D_, 0.125f * 1.4426950408889634f,
        (long long)S_ * E_, 64LL, (long long)S_ * E_, 64LL,
        (long long)H_ * SSLL, SSLL);

    // 5) softmax over heads (exp2 domain), in place
    softmax_heads16_kernel<<<(unsigned)(B_ * SSLL / 512), 256>>>(sc16);

    // 6) ctx[b,q,h*64+d] = attn @ vt^T (fp16 single), out split-bf16
    gemm_mma<64, false><<<dim3(1, S_ / 128, B_ * H_), 512, SMEM_F16_64>>>(
        (const __nv_bfloat16*)sc16, nullptr, (const __nv_bfloat16*)vt16, nullptr,
        nullptr, nullptr, nullptr, chi, clo,
        S_, S_, E_, S_, 1.f,
        (long long)H_ * SSLL, SSLL, (long long)E_ * S_, 64LL * S_,
        (long long)S_ * E_, 64LL);

    // 7) output projection -> d_out (fp32)
    gemm_mma<128, true><<<gp, 512, SMEM_SPLIT>>>(chi, clo, whi + 3 * EE, wlo + 3 * EE, bo,
        out, nullptr, nullptr, nullptr, E_, E_, E_, E_, 1.f, 0, 0, 0, 0, 0, 0);
}

// round 6
// speedup vs baseline: 1.2721x; 1.0261x over previous
#include <cuda_runtime.h>
#include <cuda_bf16.h>
#include <cuda_fp16.h>
#include <cstdint>

#define B_   2
#define S_   2048
#define E_   1024
#define H_   16
#define D_   64
#define NTOK (B_*S_)

static constexpr long long SSLL = (long long)S_ * S_;                 // 4194304
static constexpr long long SCORES_ELEMS = (long long)B_ * H_ * SSLL;  // 134217728

// ---------------- static scratch ----------------
__device__ __nv_bfloat16 g_xhi[NTOK*E_], g_xlo[NTOK*E_];
__device__ __nv_bfloat16 g_whi[4*E_*E_], g_wlo[4*E_*E_];
__device__ __half        g_qkv16[3LL*NTOK*E_];  // q | k | v slices
__device__ __half        g_sc16[SCORES_ELEMS];  // scores*log2e/8 fp16 (exp2 domain)
__device__ __nv_bfloat16 g_chi[NTOK*E_], g_clo[NTOK*E_];

// ---------------- asm helpers ----------------
__device__ __forceinline__ uint32_t smem_u32(const void* p) {
    uint32_t a;
    asm("{ .reg .u64 t; cvta.to.shared.u64 t, %1; cvt.u32.u64 %0, t; }" : "=r"(a) : "l"(p));
    return a;
}
__device__ __forceinline__ void cp16(uint32_t dst, const void* src) {
    asm volatile("cp.async.cg.shared.global [%0], [%1], 16;" :: "r"(dst), "l"(src));
}
__device__ __forceinline__ void cp_commit() { asm volatile("cp.async.commit_group;"); }
__device__ __forceinline__ void cp_wait1()  { asm volatile("cp.async.wait_group 1;"); }
__device__ __forceinline__ void ldsm4(uint32_t* r, uint32_t addr) {
    asm volatile("ldmatrix.sync.aligned.m8n8.x4.shared.b16 {%0,%1,%2,%3}, [%4];"
        : "=r"(r[0]), "=r"(r[1]), "=r"(r[2]), "=r"(r[3]) : "r"(addr));
}
__device__ __forceinline__ void ldsm4t(uint32_t* r, uint32_t addr) {
    asm volatile("ldmatrix.sync.aligned.m8n8.x4.trans.shared.b16 {%0,%1,%2,%3}, [%4];"
        : "=r"(r[0]), "=r"(r[1]), "=r"(r[2]), "=r"(r[3]) : "r"(addr));
}
__device__ __forceinline__ void mma_bf16(float* d, const uint32_t* a, const uint32_t* b) {
    asm volatile("mma.sync.aligned.m16n8k16.row.col.f32.bf16.bf16.f32 "
        "{%0,%1,%2,%3}, {%4,%5,%6,%7}, {%8,%9}, {%0,%1,%2,%3};"
        : "+f"(d[0]), "+f"(d[1]), "+f"(d[2]), "+f"(d[3])
        : "r"(a[0]), "r"(a[1]), "r"(a[2]), "r"(a[3]), "r"(b[0]), "r"(b[1]));
}
__device__ __forceinline__ void mma_f16(float* d, const uint32_t* a, const uint32_t* b) {
    asm volatile("mma.sync.aligned.m16n8k16.row.col.f32.f16.f16.f32 "
        "{%0,%1,%2,%3}, {%4,%5,%6,%7}, {%8,%9}, {%0,%1,%2,%3};"
        : "+f"(d[0]), "+f"(d[1]), "+f"(d[2]), "+f"(d[3])
        : "r"(a[0]), "r"(a[1]), "r"(a[2]), "r"(a[3]), "r"(b[0]), "r"(b[1]));
}

// ---------------- utility kernels ----------------
__global__ void split_kernel(const float* __restrict__ src,
                             __nv_bfloat16* __restrict__ hi,
                             __nv_bfloat16* __restrict__ lo, int n) {
    for (int i = blockIdx.x * 256 + threadIdx.x; i < n; i += gridDim.x * 256) {
        float f = src[i];
        __nv_bfloat16 h = __float2bfloat16(f);
        hi[i] = h;
        lo[i] = __float2bfloat16(f - __bfloat162float(h));
    }
}

// all four weight matrices in one launch (blockIdx.y selects)
__global__ void split4_kernel(const float* __restrict__ w0, const float* __restrict__ w1,
                              const float* __restrict__ w2, const float* __restrict__ w3,
                              __nv_bfloat16* __restrict__ hi, __nv_bfloat16* __restrict__ lo) {
    const int z = blockIdx.y;
    const float* src = (z == 0) ? w0 : (z == 1) ? w1 : (z == 2) ? w2 : w3;
    const int off = z * (E_ * E_);
    for (int i = blockIdx.x * 256 + threadIdx.x; i < E_ * E_; i += gridDim.x * 256) {
        float f = src[i];
        __nv_bfloat16 h = __float2bfloat16(f);
        hi[off + i] = h;
        lo[off + i] = __float2bfloat16(f - __bfloat162float(h));
    }
}

// ---------------- mma.sync GEMM ----------------
// C = scale*(A @ B^T) + bias; SPLIT: bf16 hi/lo 3-term; else fp16 single.
// bias selected per-zh from {bias0,bias1,bias2} (for the fused qkv launch).
template <int BN, bool SPLIT>
__global__ __launch_bounds__(512)
void gemm_mma(const __nv_bfloat16* __restrict__ Ahi, const __nv_bfloat16* __restrict__ Alo,
              const __nv_bfloat16* __restrict__ Bhi, const __nv_bfloat16* __restrict__ Blo,
              const float* __restrict__ bias0, const float* __restrict__ bias1,
              const float* __restrict__ bias2,
              float* __restrict__ Cf, __half* __restrict__ C16,
              __nv_bfloat16* __restrict__ Chi, __nv_bfloat16* __restrict__ Clo,
              int lda, int ldb, int ldc, int K, float scale,
              long long aB, long long aH, long long bB, long long bH,
              long long cB, long long cH)
{
    extern __shared__ char smem[];
    constexpr int ASZ = 128 * 80;
    constexpr int BSZ = BN * 80;
    constexpr int OFF_ALO = ASZ;
    constexpr int OFF_BHI = SPLIT ? 2 * ASZ : ASZ;
    constexpr int OFF_BLO = OFF_BHI + BSZ;
    constexpr int STAGE   = OFF_BHI + (SPLIT ? 2 : 1) * BSZ;
    constexpr int NT = BN / 16;

    const int tid  = threadIdx.x;
    const int lane = tid & 31;
    const int wid  = tid >> 5;
    const int wm   = wid & 7;
    const int wn   = wid >> 3;
    const int zb = blockIdx.z >> 4, zh = blockIdx.z & 15;
    const uint32_t sb = smem_u32(smem);
    const float* bias = (zh == 1) ? bias1 : ((zh == 2) ? bias2 : bias0);

    const __nv_bfloat16* pAhi = Ahi + zb * aB + zh * aH + (long long)blockIdx.y * 128 * lda;
    const __nv_bfloat16* pAlo = SPLIT ? (Alo + zb * aB + zh * aH + (long long)blockIdx.y * 128 * lda) : nullptr;
    const __nv_bfloat16* pBhi = Bhi + zb * bB + zh * bH + (long long)blockIdx.x * BN * ldb;
    const __nv_bfloat16* pBlo = SPLIT ? (Blo + zb * bB + zh * bH + (long long)blockIdx.x * BN * ldb) : nullptr;

    const int arow = tid >> 2, ac = tid & 3;
    const int brow = tid >> 2, bc = tid & 3;

    auto load_stage = [&](int kb, int stg) {
        uint32_t s0 = sb + stg * STAGE;
        {
            long long g = (long long)arow * lda + kb * 32 + ac * 8;
            uint32_t d = s0 + arow * 80 + ac * 16;
            cp16(d, pAhi + g);
            if (SPLIT) cp16(d + OFF_ALO, pAlo + g);
        }
        if (BN == 128 || tid < BN * 4) {
            long long g = (long long)brow * ldb + kb * 32 + bc * 8;
            uint32_t d = s0 + OFF_BHI + brow * 80 + bc * 16;
            cp16(d, pBhi + g);
            if (SPLIT) cp16(d + (OFF_BLO - OFF_BHI), pBlo + g);
        }
    };

    const int KI = K >> 5;
    load_stage(0, 0); cp_commit();
    load_stage(1, 1); cp_commit();

    float acc[NT][4];
#pragma unroll
    for (int t = 0; t < NT; t++)
#pragma unroll
        for (int i = 0; i < 4; i++) acc[t][i] = 0.f;

    const int a_r = wm * 16 + (lane & 15);
    const int a_c = (lane >> 4) * 16;
    const int b_r = wn * (BN / 2) + (lane & 7) + ((lane >> 4) & 1) * 8;
    const int b_c = ((lane >> 3) & 1) * 16;

    for (int kb = 0; kb < KI; kb++) {
        cp_wait1();
        __syncthreads();
        const uint32_t s0 = sb + (kb & 1) * STAGE;
#pragma unroll
        for (int ks = 0; ks < 2; ks++) {
            const uint32_t koff = ks * 32;
            uint32_t ah[4], bh[NT * 2];
            ldsm4(ah, s0 + a_r * 80 + a_c + koff);
#pragma unroll
            for (int t2 = 0; t2 < NT / 2; t2++) {
                uint32_t r4[4];
                ldsm4(r4, s0 + OFF_BHI + (b_r + t2 * 16) * 80 + b_c + koff);
                bh[t2*4+0] = r4[0]; bh[t2*4+1] = r4[1]; bh[t2*4+2] = r4[2]; bh[t2*4+3] = r4[3];
            }
            if (SPLIT) {
#pragma unroll
                for (int t = 0; t < NT; t++) mma_bf16(acc[t], ah, &bh[t * 2]);
                uint32_t bl[NT * 2];
#pragma unroll
                for (int t2 = 0; t2 < NT / 2; t2++) {
                    uint32_t r4[4];
                    ldsm4(r4, s0 + OFF_BLO + (b_r + t2 * 16) * 80 + b_c + koff);
                    bl[t2*4+0] = r4[0]; bl[t2*4+1] = r4[1]; bl[t2*4+2] = r4[2]; bl[t2*4+3] = r4[3];
                }
#pragma unroll
                for (int t = 0; t < NT; t++) mma_bf16(acc[t], ah, &bl[t * 2]);
                uint32_t al[4];
                ldsm4(al, s0 + OFF_ALO + a_r * 80 + a_c + koff);
#pragma unroll
                for (int t = 0; t < NT; t++) mma_bf16(acc[t], al, &bh[t * 2]);
            } else {
#pragma unroll
                for (int t = 0; t < NT; t++) mma_f16(acc[t], ah, &bh[t * 2]);
            }
        }
        __syncthreads();
        if (kb + 2 < KI) load_stage(kb + 2, kb & 1);
        cp_commit();
    }

    const int mrow = blockIdx.y * 128 + wm * 16 + (lane >> 2);
    const int ncol0 = blockIdx.x * BN + wn * (BN / 2);
    const long long cb = zb * cB + zh * cH;
#pragma unroll
    for (int t = 0; t < NT; t++) {
        const int col = ncol0 + t * 8 + (lane & 3) * 2;
        float v0 = acc[t][0] * scale, v1 = acc[t][1] * scale;
        float v2 = acc[t][2] * scale, v3 = acc[t][3] * scale;
        if (bias) {
            float b0 = __ldg(&bias[col]), b1 = __ldg(&bias[col + 1]);
            v0 += b0; v1 += b1; v2 += b0; v3 += b1;
        }
        if (Cf) {
            *(float2*)(Cf + cb + (long long)mrow * ldc + col)       = make_float2(v0, v1);
            *(float2*)(Cf + cb + (long long)(mrow + 8) * ldc + col) = make_float2(v2, v3);
        } else if (C16) {
            __half2 p0; p0.x = __float2half(v0); p0.y = __float2half(v1);
            __half2 p1; p1.x = __float2half(v2); p1.y = __float2half(v3);
            *(__half2*)(C16 + cb + (long long)mrow * ldc + col)       = p0;
            *(__half2*)(C16 + cb + (long long)(mrow + 8) * ldc + col) = p1;
        } else {
            __nv_bfloat16 h0 = __float2bfloat16(v0), h1 = __float2bfloat16(v1);
            __nv_bfloat16 h2 = __float2bfloat16(v2), h3 = __float2bfloat16(v3);
            __nv_bfloat162 hp0; hp0.x = h0; hp0.y = h1;
            __nv_bfloat162 hp1; hp1.x = h2; hp1.y = h3;
            __nv_bfloat162 lp0; lp0.x = __float2bfloat16(v0 - __bfloat162float(h0));
                                lp0.y = __float2bfloat16(v1 - __bfloat162float(h1));
            __nv_bfloat162 lp1; lp1.x = __float2bfloat16(v2 - __bfloat162float(h2));
                                lp1.y = __float2bfloat16(v3 - __bfloat162float(h3));
            *(__nv_bfloat162*)(Chi + cb + (long long)mrow * ldc + col)       = hp0;
            *(__nv_bfloat162*)(Chi + cb + (long long)(mrow + 8) * ldc + col) = hp1;
            *(__nv_bfloat162*)(Clo + cb + (long long)mrow * ldc + col)       = lp0;
            *(__nv_bfloat162*)(Clo + cb + (long long)(mrow + 8) * ldc + col) = lp1;
        }
    }
}

// ---------------- fused heads-softmax + PV ----------------
// Block: 32 queries x 16 heads (warp = head), 512 threads, k-tiles of 32.
// sc16 in exp2 domain; V read directly from v16 [token][e] via ldmatrix.trans.
#define FQ 32
#define FK 32
#define F_SC_ROW 80
#define F_V_ROW  144
#define F_SC_SZ  (512*F_SC_ROW)        // 40960
#define F_V_SZ   (512*F_V_ROW)         // 73728
#define F_STAGE  (F_SC_SZ + F_V_SZ)    // 114688
#define F_SMEM   (2*F_STAGE)           // 229376

__global__ __launch_bounds__(512, 1)
void attn_pv(const __half* __restrict__ sc16, const __half* __restrict__ v16,
             __nv_bfloat16* __restrict__ chi, __nv_bfloat16* __restrict__ clo)
{
    extern __shared__ char smem[];
    const int tid = threadIdx.x, lane = tid & 31, wid = tid >> 5;  // wid = head
    const int b = blockIdx.y, q0 = blockIdx.x * FQ;
    const uint32_t sb = smem_u32(smem);

    auto load_sc = [&](int kt, int stg) {
#pragma unroll
        for (int p = 0; p < 4; p++) {
            int idx = tid + p * 512, r = idx >> 2, c = idx & 3;   // r: h*32+q
            int h = r >> 5, q = r & 31;
            long long g = (((long long)(b * H_ + h)) * S_ + q0 + q) * S_ + kt * FK + c * 8;
            cp16(sb + stg * F_STAGE + r * F_SC_ROW + c * 16, sc16 + g);
        }
    };
    auto load_v = [&](int kt, int stg) {
#pragma unroll
        for (int p = 0; p < 8; p++) {
            int idx = tid + p * 512, r = idx >> 3, c = idx & 7;   // r: h*32+k
            int h = r >> 5, k = r & 31;
            long long g = ((long long)(b * S_ + kt * FK + k)) * E_ + h * 64 + c * 8;
            cp16(sb + stg * F_STAGE + F_SC_SZ + r * F_V_ROW + c * 16, v16 + g);
        }
    };

    load_sc(0, 0); load_v(0, 0); cp_commit();
    load_sc(1, 1); load_v(1, 1); cp_commit();

    float acc[2][8][4] = {};
    const int sq = tid >> 4, sk4 = (tid & 15) * 4;   // softmax: (q, k-pair)

    for (int kt = 0; kt < S_ / FK; kt++) {
        cp_wait1();
        __syncthreads();
        const int stg = kt & 1;
        const uint32_t scb  = sb + stg * F_STAGE;
        const uint32_t vbuf = scb + F_SC_SZ;

        // softmax over the 16 heads at (sq, 2 k's), exps kept in registers
        {
            const uint32_t a0 = scb + sq * F_SC_ROW + sk4;
            float s0 = 0.f, s1 = 0.f;
            __half2 e2[H_];
#pragma unroll
            for (int h = 0; h < H_; h++) {
                uint32_t raw;
                asm volatile("ld.shared.b32 %0, [%1];" : "=r"(raw) : "r"(a0 + h * (32 * F_SC_ROW)));
                float2 f = __half22float2(*(__half2*)&raw);
                f.x = exp2f(f.x); f.y = exp2f(f.y);
                s0 += f.x; s1 += f.y;
                e2[h] = __floats2half2_rn(f.x, f.y);
            }
            const float i0 = 1.f / s0, i1 = 1.f / s1;
#pragma unroll
            for (int h = 0; h < H_; h++) {
                float2 g = __half22float2(e2[h]);
                __half2 r = __floats2half2_rn(g.x * i0, g.y * i1);
                asm volatile("st.shared.b32 [%0], %1;" :: "r"(a0 + h * (32 * F_SC_ROW)), "r"(*(uint32_t*)&r));
            }
        }
        __syncthreads();

        // PV: warp = head
        const uint32_t pa = scb + wid * (32 * F_SC_ROW);
        const uint32_t va = vbuf + wid * (32 * F_V_ROW);
        uint32_t afr[2][2][4];
#pragma unroll
        for (int m = 0; m < 2; m++)
#pragma unroll
            for (int ks = 0; ks < 2; ks++)
                ldsm4(afr[m][ks], pa + (m * 16 + (lane & 15)) * F_SC_ROW + (lane >> 4) * 16 + ks * 32);
#pragma unroll
        for (int ks = 0; ks < 2; ks++)
#pragma unroll
            for (int nt2 = 0; nt2 < 4; nt2++) {
                uint32_t bf[4];
                ldsm4t(bf, va + (ks * 16 + (lane & 15)) * F_V_ROW + nt2 * 32 + (lane >> 4) * 16);
                mma_f16(acc[0][nt2 * 2],     afr[0][ks], bf);
                mma_f16(acc[0][nt2 * 2 + 1], afr[0][ks], bf + 2);
                mma_f16(acc[1][nt2 * 2],     afr[1][ks], bf);
                mma_f16(acc[1][nt2 * 2 + 1], afr[1][ks], bf + 2);
            }
        __syncthreads();
        if (kt + 2 < S_ / FK) { load_sc(kt + 2, stg); load_v(kt + 2, stg); }
        cp_commit();
    }

    // epilogue: ctx[b][q][wid*64+d] split-bf16
    const int col0 = wid * 64 + (lane & 3) * 2;
#pragma unroll
    for (int m = 0; m < 2; m++) {
        const int row = q0 + m * 16 + (lane >> 2);
#pragma unroll
        for (int n = 0; n < 8; n++) {
            const int col = col0 + n * 8;
            float v0 = acc[m][n][0], v1 = acc[m][n][1];
            float v2 = acc[m][n][2], v3 = acc[m][n][3];
            __nv_bfloat16 h0 = __float2bfloat16(v0), h1 = __float2bfloat16(v1);
            __nv_bfloat16 h2 = __float2bfloat16(v2), h3 = __float2bfloat16(v3);
            __nv_bfloat162 hp0; hp0.x = h0; hp0.y = h1;
            __nv_bfloat162 hp1; hp1.x = h2; hp1.y = h3;
            __nv_bfloat162 lp0; lp0.x = __float2bfloat16(v0 - __bfloat162float(h0));
                                lp0.y = __float2bfloat16(v1 - __bfloat162float(h1));
            __nv_bfloat162 lp1; lp1.x = __float2bfloat16(v2 - __bfloat162float(h2));
                                lp1.y = __float2bfloat16(v3 - __bfloat162float(h3));
            long long o0 = ((long long)(b * S_ + row)) * E_ + col;
            long long o1 = ((long long)(b * S_ + row + 8)) * E_ + col;
            *(__nv_bfloat162*)(chi + o0) = hp0;
            *(__nv_bfloat162*)(chi + o1) = hp1;
            *(__nv_bfloat162*)(clo + o0) = lp0;
            *(__nv_bfloat162*)(clo + o1) = lp1;
        }
    }
}

// ---------------- launch ----------------
extern "C" void kernel_launch(void* const* d_in, const int* in_sizes, int n_in,
                              void* d_out, int out_size)
{
    const float* x  = (const float*)d_in[0];
    const float* Wq = (const float*)d_in[1];
    const float* bq = (const float*)d_in[2];
    const float* Wk = (const float*)d_in[3];
    const float* bk = (const float*)d_in[4];
    const float* Wv = (const float*)d_in[5];
    const float* bv = (const float*)d_in[6];
    const float* Wo = (const float*)d_in[7];
    const float* bo = (const float*)d_in[8];
    float* out = (float*)d_out;

    __nv_bfloat16 *xhi, *xlo, *whi, *wlo, *chi, *clo;
    __half *qkv16, *sc16;
    cudaGetSymbolAddress((void**)&xhi, g_xhi);  cudaGetSymbolAddress((void**)&xlo, g_xlo);
    cudaGetSymbolAddress((void**)&whi, g_whi);  cudaGetSymbolAddress((void**)&wlo, g_wlo);
    cudaGetSymbolAddress((void**)&qkv16, g_qkv16);
    cudaGetSymbolAddress((void**)&sc16, g_sc16);
    cudaGetSymbolAddress((void**)&chi, g_chi);  cudaGetSymbolAddress((void**)&clo, g_clo);

    constexpr int SMEM_SPLIT   = 2 * (2 * 128 * 80 + 2 * 128 * 80);  // 81920
    constexpr int SMEM_F16_128 = 2 * (128 * 80 + 128 * 80);          // 40960
    cudaFuncSetAttribute(gemm_mma<128, true>, cudaFuncAttributeMaxDynamicSharedMemorySize, SMEM_SPLIT);
    cudaFuncSetAttribute(attn_pv, cudaFuncAttributeMaxDynamicSharedMemorySize, F_SMEM);

    const int EE = E_ * E_;
    const long long QKV = (long long)NTOK * E_;
    __half* q16 = qkv16;
    __half* k16 = qkv16 + QKV;
    __half* v16 = qkv16 + 2 * QKV;

    // 1) split fp32 -> bf16 hi/lo (x, then all 4 weights in one launch)
    split_kernel<<<2048, 256>>>(x, xhi, xlo, NTOK * E_);
    split4_kernel<<<dim3(256, 4), 256>>>(Wq, Wk, Wv, Wo, whi, wlo);

    // 2) q,k,v projections fused into one launch (z selects W/bias/output slice)
    gemm_mma<128, true><<<dim3(E_ / 128, NTOK / 128, 3), 512, SMEM_SPLIT>>>(
        xhi, xlo, whi, wlo, bq, bk, bv,
        nullptr, qkv16, nullptr, nullptr, E_, E_, E_, E_, 1.f,
        0, 0, 0, (long long)EE, 0, QKV);

    // 3) scores[b,h,q,k] = (q.k)*(log2e/8), fp16 single-term, fp16 out
    gemm_mma<128, false><<<dim3(S_ / 128, S_ / 128, B_ * H_), 512, SMEM_F16_128>>>(
        (const __nv_bfloat16*)q16, nullptr, (const __nv_bfloat16*)k16, nullptr,
        nullptr, nullptr, nullptr, nullptr, sc16, nullptr, nullptr,
        E_, E_, S_, D_, 0.125f * 1.4426950408889634f,
        (long long)S_ * E_, 64LL, (long long)S_ * E_, 64LL,
        (long long)H_ * SSLL, SSLL);

    // 4) fused heads-softmax + PV -> ctx split-bf16
    attn_pv<<<dim3(S_ / FQ, B_), 512, F_SMEM>>>(sc16, v16, chi, clo);

    // 5) output projection -> d_out (fp32)
    gemm_mma<128, true><<<dim3(E_ / 128, NTOK / 128, 1), 512, SMEM_SPLIT>>>(
        chi, clo, whi + 3 * EE, wlo + 3 * EE, bo, nullptr, nullptr,
        out, nullptr, nullptr, nullptr, E_, E_, E_, E_, 1.f, 0, 0, 0, 0, 0, 0);
}

// round 7
// speedup vs baseline: 1.4140x; 1.1116x over previous
#include <cuda_runtime.h>
#include <cuda_bf16.h>
#include <cuda_fp16.h>
#include <cstdint>

#define B_   2
#define S_   2048
#define E_   1024
#define H_   16
#define D_   64
#define NTOK (B_*S_)

static constexpr long long SSLL = (long long)S_ * S_;                 // 4194304
static constexpr long long SCORES_ELEMS = (long long)B_ * H_ * SSLL;  // 134217728

// ---------------- static scratch ----------------
__device__ __nv_bfloat16 g_xhi[NTOK*E_], g_xlo[NTOK*E_];
__device__ __nv_bfloat16 g_whi[4*E_*E_], g_wlo[4*E_*E_];
__device__ __half        g_qkv16[3LL*NTOK*E_];  // q | k | v slices
__device__ __half        g_sc16[SCORES_ELEMS];  // scores*log2e/8 fp16 (exp2 domain)
__device__ __nv_bfloat16 g_chi[NTOK*E_], g_clo[NTOK*E_];

// ---------------- asm helpers ----------------
__device__ __forceinline__ uint32_t smem_u32(const void* p) {
    uint32_t a;
    asm("{ .reg .u64 t; cvta.to.shared.u64 t, %1; cvt.u32.u64 %0, t; }" : "=r"(a) : "l"(p));
    return a;
}
__device__ __forceinline__ void cp16(uint32_t dst, const void* src) {
    asm volatile("cp.async.cg.shared.global [%0], [%1], 16;" :: "r"(dst), "l"(src));
}
__device__ __forceinline__ void cp_commit() { asm volatile("cp.async.commit_group;"); }
__device__ __forceinline__ void cp_wait1()  { asm volatile("cp.async.wait_group 1;"); }
__device__ __forceinline__ void ldsm4(uint32_t* r, uint32_t addr) {
    asm volatile("ldmatrix.sync.aligned.m8n8.x4.shared.b16 {%0,%1,%2,%3}, [%4];"
        : "=r"(r[0]), "=r"(r[1]), "=r"(r[2]), "=r"(r[3]) : "r"(addr));
}
__device__ __forceinline__ void ldsm4t(uint32_t* r, uint32_t addr) {
    asm volatile("ldmatrix.sync.aligned.m8n8.x4.trans.shared.b16 {%0,%1,%2,%3}, [%4];"
        : "=r"(r[0]), "=r"(r[1]), "=r"(r[2]), "=r"(r[3]) : "r"(addr));
}
__device__ __forceinline__ void mma_bf16(float* d, const uint32_t* a, const uint32_t* b) {
    asm volatile("mma.sync.aligned.m16n8k16.row.col.f32.bf16.bf16.f32 "
        "{%0,%1,%2,%3}, {%4,%5,%6,%7}, {%8,%9}, {%0,%1,%2,%3};"
        : "+f"(d[0]), "+f"(d[1]), "+f"(d[2]), "+f"(d[3])
        : "r"(a[0]), "r"(a[1]), "r"(a[2]), "r"(a[3]), "r"(b[0]), "r"(b[1]));
}
__device__ __forceinline__ void mma_f16(float* d, const uint32_t* a, const uint32_t* b) {
    asm volatile("mma.sync.aligned.m16n8k16.row.col.f32.f16.f16.f32 "
        "{%0,%1,%2,%3}, {%4,%5,%6,%7}, {%8,%9}, {%0,%1,%2,%3};"
        : "+f"(d[0]), "+f"(d[1]), "+f"(d[2]), "+f"(d[3])
        : "r"(a[0]), "r"(a[1]), "r"(a[2]), "r"(a[3]), "r"(b[0]), "r"(b[1]));
}

// ---------------- utility kernels ----------------
__global__ void split_kernel(const float* __restrict__ src,
                             __nv_bfloat16* __restrict__ hi,
                             __nv_bfloat16* __restrict__ lo, int n) {
    for (int i = blockIdx.x * 256 + threadIdx.x; i < n; i += gridDim.x * 256) {
        float f = src[i];
        __nv_bfloat16 h = __float2bfloat16(f);
        hi[i] = h;
        lo[i] = __float2bfloat16(f - __bfloat162float(h));
    }
}

__global__ void split4_kernel(const float* __restrict__ w0, const float* __restrict__ w1,
                              const float* __restrict__ w2, const float* __restrict__ w3,
                              __nv_bfloat16* __restrict__ hi, __nv_bfloat16* __restrict__ lo) {
    const int z = blockIdx.y;
    const float* src = (z == 0) ? w0 : (z == 1) ? w1 : (z == 2) ? w2 : w3;
    const int off = z * (E_ * E_);
    for (int i = blockIdx.x * 256 + threadIdx.x; i < E_ * E_; i += gridDim.x * 256) {
        float f = src[i];
        __nv_bfloat16 h = __float2bfloat16(f);
        hi[off + i] = h;
        lo[off + i] = __float2bfloat16(f - __bfloat162float(h));
    }
}

// ---------------- split-bf16 mma GEMM (projections) ----------------
template <int BN, bool SPLIT>
__global__ __launch_bounds__(512)
void gemm_mma(const __nv_bfloat16* __restrict__ Ahi, const __nv_bfloat16* __restrict__ Alo,
              const __nv_bfloat16* __restrict__ Bhi, const __nv_bfloat16* __restrict__ Blo,
              const float* __restrict__ bias0, const float* __restrict__ bias1,
              const float* __restrict__ bias2,
              float* __restrict__ Cf, __half* __restrict__ C16,
              __nv_bfloat16* __restrict__ Chi, __nv_bfloat16* __restrict__ Clo,
              int lda, int ldb, int ldc, int K, float scale,
              long long aB, long long aH, long long bB, long long bH,
              long long cB, long long cH)
{
    extern __shared__ char smem[];
    constexpr int ASZ = 128 * 80;
    constexpr int BSZ = BN * 80;
    constexpr int OFF_ALO = ASZ;
    constexpr int OFF_BHI = SPLIT ? 2 * ASZ : ASZ;
    constexpr int OFF_BLO = OFF_BHI + BSZ;
    constexpr int STAGE   = OFF_BHI + (SPLIT ? 2 : 1) * BSZ;
    constexpr int NT = BN / 16;

    const int tid  = threadIdx.x;
    const int lane = tid & 31;
    const int wid  = tid >> 5;
    const int wm   = wid & 7;
    const int wn   = wid >> 3;
    const int zb = blockIdx.z >> 4, zh = blockIdx.z & 15;
    const uint32_t sb = smem_u32(smem);
    const float* bias = (zh == 1) ? bias1 : ((zh == 2) ? bias2 : bias0);

    const __nv_bfloat16* pAhi = Ahi + zb * aB + zh * aH + (long long)blockIdx.y * 128 * lda;
    const __nv_bfloat16* pAlo = SPLIT ? (Alo + zb * aB + zh * aH + (long long)blockIdx.y * 128 * lda) : nullptr;
    const __nv_bfloat16* pBhi = Bhi + zb * bB + zh * bH + (long long)blockIdx.x * BN * ldb;
    const __nv_bfloat16* pBlo = SPLIT ? (Blo + zb * bB + zh * bH + (long long)blockIdx.x * BN * ldb) : nullptr;

    const int arow = tid >> 2, ac = tid & 3;
    const int brow = tid >> 2, bc = tid & 3;

    auto load_stage = [&](int kb, int stg) {
        uint32_t s0 = sb + stg * STAGE;
        {
            long long g = (long long)arow * lda + kb * 32 + ac * 8;
            uint32_t d = s0 + arow * 80 + ac * 16;
            cp16(d, pAhi + g);
            if (SPLIT) cp16(d + OFF_ALO, pAlo + g);
        }
        if (BN == 128 || tid < BN * 4) {
            long long g = (long long)brow * ldb + kb * 32 + bc * 8;
            uint32_t d = s0 + OFF_BHI + brow * 80 + bc * 16;
            cp16(d, pBhi + g);
            if (SPLIT) cp16(d + (OFF_BLO - OFF_BHI), pBlo + g);
        }
    };

    const int KI = K >> 5;
    load_stage(0, 0); cp_commit();
    load_stage(1, 1); cp_commit();

    float acc[NT][4];
#pragma unroll
    for (int t = 0; t < NT; t++)
#pragma unroll
        for (int i = 0; i < 4; i++) acc[t][i] = 0.f;

    const int a_r = wm * 16 + (lane & 15);
    const int a_c = (lane >> 4) * 16;
    const int b_r = wn * (BN / 2) + (lane & 7) + ((lane >> 4) & 1) * 8;
    const int b_c = ((lane >> 3) & 1) * 16;

    for (int kb = 0; kb < KI; kb++) {
        cp_wait1();
        __syncthreads();
        const uint32_t s0 = sb + (kb & 1) * STAGE;
#pragma unroll
        for (int ks = 0; ks < 2; ks++) {
            const uint32_t koff = ks * 32;
            uint32_t ah[4], bh[NT * 2];
            ldsm4(ah, s0 + a_r * 80 + a_c + koff);
#pragma unroll
            for (int t2 = 0; t2 < NT / 2; t2++) {
                uint32_t r4[4];
                ldsm4(r4, s0 + OFF_BHI + (b_r + t2 * 16) * 80 + b_c + koff);
                bh[t2*4+0] = r4[0]; bh[t2*4+1] = r4[1]; bh[t2*4+2] = r4[2]; bh[t2*4+3] = r4[3];
            }
            if (SPLIT) {
#pragma unroll
                for (int t = 0; t < NT; t++) mma_bf16(acc[t], ah, &bh[t * 2]);
                uint32_t bl[NT * 2];
#pragma unroll
                for (int t2 = 0; t2 < NT / 2; t2++) {
                    uint32_t r4[4];
                    ldsm4(r4, s0 + OFF_BLO + (b_r + t2 * 16) * 80 + b_c + koff);
                    bl[t2*4+0] = r4[0]; bl[t2*4+1] = r4[1]; bl[t2*4+2] = r4[2]; bl[t2*4+3] = r4[3];
                }
#pragma unroll
                for (int t = 0; t < NT; t++) mma_bf16(acc[t], ah, &bl[t * 2]);
                uint32_t al[4];
                ldsm4(al, s0 + OFF_ALO + a_r * 80 + a_c + koff);
#pragma unroll
                for (int t = 0; t < NT; t++) mma_bf16(acc[t], al, &bh[t * 2]);
            } else {
#pragma unroll
                for (int t = 0; t < NT; t++) mma_f16(acc[t], ah, &bh[t * 2]);
            }
        }
        __syncthreads();
        if (kb + 2 < KI) load_stage(kb + 2, kb & 1);
        cp_commit();
    }

    const int mrow = blockIdx.y * 128 + wm * 16 + (lane >> 2);
    const int ncol0 = blockIdx.x * BN + wn * (BN / 2);
    const long long cb = zb * cB + zh * cH;
#pragma unroll
    for (int t = 0; t < NT; t++) {
        const int col = ncol0 + t * 8 + (lane & 3) * 2;
        float v0 = acc[t][0] * scale, v1 = acc[t][1] * scale;
        float v2 = acc[t][2] * scale, v3 = acc[t][3] * scale;
        if (bias) {
            float b0 = __ldg(&bias[col]), b1 = __ldg(&bias[col + 1]);
            v0 += b0; v1 += b1; v2 += b0; v3 += b1;
        }
        if (Cf) {
            *(float2*)(Cf + cb + (long long)mrow * ldc + col)       = make_float2(v0, v1);
            *(float2*)(Cf + cb + (long long)(mrow + 8) * ldc + col) = make_float2(v2, v3);
        } else if (C16) {
            __half2 p0; p0.x = __float2half(v0); p0.y = __float2half(v1);
            __half2 p1; p1.x = __float2half(v2); p1.y = __float2half(v3);
            *(__half2*)(C16 + cb + (long long)mrow * ldc + col)       = p0;
            *(__half2*)(C16 + cb + (long long)(mrow + 8) * ldc + col) = p1;
        } else {
            __nv_bfloat16 h0 = __float2bfloat16(v0), h1 = __float2bfloat16(v1);
            __nv_bfloat16 h2 = __float2bfloat16(v2), h3 = __float2bfloat16(v3);
            __nv_bfloat162 hp0; hp0.x = h0; hp0.y = h1;
            __nv_bfloat162 hp1; hp1.x = h2; hp1.y = h3;
            __nv_bfloat162 lp0; lp0.x = __float2bfloat16(v0 - __bfloat162float(h0));
                                lp0.y = __float2bfloat16(v1 - __bfloat162float(h1));
            __nv_bfloat162 lp1; lp1.x = __float2bfloat16(v2 - __bfloat162float(h2));
                                lp1.y = __float2bfloat16(v3 - __bfloat162float(h3));
            *(__nv_bfloat162*)(Chi + cb + (long long)mrow * ldc + col)       = hp0;
            *(__nv_bfloat162*)(Chi + cb + (long long)(mrow + 8) * ldc + col) = hp1;
            *(__nv_bfloat162*)(Clo + cb + (long long)mrow * ldc + col)       = lp0;
            *(__nv_bfloat162*)(Clo + cb + (long long)(mrow + 8) * ldc + col) = lp1;
        }
    }
}

// ---------------- dedicated scores kernel ----------------
// Block: one (b,h, 64-q tile); streams all 16 k-tiles of 128.
// q-tile (64x64 fp16) in smem once; A-fragments hoisted to registers.
// 256 threads: 4 m-warps x 2 n-warps; warp tile 16m x 64n x 64k per k-tile.
// Writes sc16[(b,h,q,k)] = fp16( q.k * log2e/8 ).
#define SCR_AROW 144
#define SCR_ASZ  (64*SCR_AROW)          // 9216
#define SCR_BSZ  (128*SCR_AROW)         // 18432
#define SCR_SMEM (SCR_ASZ + 2*SCR_BSZ)  // 46080

__global__ __launch_bounds__(256, 3)
void score_gemm(const __half* __restrict__ q16, const __half* __restrict__ k16,
                __half* __restrict__ sc16)
{
    extern __shared__ char smem[];
    const int tid = threadIdx.x, lane = tid & 31, wid = tid >> 5;
    const int wm = wid & 3, wn = wid >> 2;
    const int bz = blockIdx.z;                  // b*16+h
    const int b = bz >> 4, h = bz & 15;
    const int q0 = blockIdx.x * 64;
    const uint32_t sb = smem_u32(smem);
    const uint32_t sbB = sb + SCR_ASZ;
    const float scale = 0.125f * 1.4426950408889634f;

    const __half* qp = q16 + ((long long)b * S_ + q0) * E_ + h * 64;
    const __half* kp = k16 + (long long)b * S_ * E_ + h * 64;

    // A: 64 rows x 8 chunks = 512; 2 per thread
    auto load_a = [&]() {
#pragma unroll
        for (int p = 0; p < 2; p++) {
            int idx = tid + p * 256, r = idx >> 3, c = idx & 7;
            cp16(sb + r * SCR_AROW + c * 16, qp + (long long)r * E_ + c * 8);
        }
    };
    // B-tile kt: 128 rows x 8 chunks = 1024; 4 per thread
    auto load_b = [&](int kt, int stg) {
        const __half* base = kp + (long long)kt * 128 * E_;
#pragma unroll
        for (int p = 0; p < 4; p++) {
            int idx = tid + p * 256, r = idx >> 3, c = idx & 7;
            cp16(sbB + stg * SCR_BSZ + r * SCR_AROW + c * 16, base + (long long)r * E_ + c * 8);
        }
    };

    load_a(); load_b(0, 0); cp_commit();
    load_b(1, 1); cp_commit();

    const int a_r = wm * 16 + (lane & 15);
    const int a_c = (lane >> 4) * 16;
    const int b_r = wn * 64 + (lane & 7) + ((lane >> 4) & 1) * 8;
    const int b_c = ((lane >> 3) & 1) * 16;

    uint32_t afr[4][4];
    const int mrow = q0 + wm * 16 + (lane >> 2);
    const long long obase = ((long long)bz * S_ + mrow) * S_;
    const int col0 = wn * 64 + (lane & 3) * 2;

    for (int kt = 0; kt < S_ / 128; kt++) {
        cp_wait1();
        __syncthreads();
        if (kt == 0) {
#pragma unroll
            for (int ks = 0; ks < 4; ks++)
                ldsm4(afr[ks], sb + a_r * SCR_AROW + a_c + ks * 32);
        }
        const uint32_t s0 = sbB + (kt & 1) * SCR_BSZ;
        float acc[8][4] = {};
#pragma unroll
        for (int ks = 0; ks < 4; ks++) {
#pragma unroll
            for (int nt2 = 0; nt2 < 4; nt2++) {
                uint32_t bf[4];
                ldsm4(bf, s0 + (b_r + nt2 * 16) * SCR_AROW + b_c + ks * 32);
                mma_f16(acc[nt2 * 2],     afr[ks], bf);
                mma_f16(acc[nt2 * 2 + 1], afr[ks], bf + 2);
            }
        }
        __syncthreads();
        if (kt + 2 < S_ / 128) load_b(kt + 2, kt & 1);
        cp_commit();

        // write this 64x128 fp16 tile
        const long long ob = obase + kt * 128;
#pragma unroll
        for (int t = 0; t < 8; t++) {
            const int col = col0 + t * 8;
            __half2 p0; p0.x = __float2half(acc[t][0] * scale); p0.y = __float2half(acc[t][1] * scale);
            __half2 p1; p1.x = __float2half(acc[t][2] * scale); p1.y = __float2half(acc[t][3] * scale);
            *(__half2*)(sc16 + ob + col)            = p0;
            *(__half2*)(sc16 + ob + 8LL * S_ + col) = p1;
        }
    }
}

// ---------------- fused heads-softmax + PV ----------------
#define FQ 32
#define FK 32
#define F_SC_ROW 80
#define F_V_ROW  144
#define F_SC_SZ  (512*F_SC_ROW)        // 40960
#define F_V_SZ   (512*F_V_ROW)         // 73728
#define F_STAGE  (F_SC_SZ + F_V_SZ)    // 114688
#define F_SMEM   (2*F_STAGE)           // 229376

__global__ __launch_bounds__(512, 1)
void attn_pv(const __half* __restrict__ sc16, const __half* __restrict__ v16,
             __nv_bfloat16* __restrict__ chi, __nv_bfloat16* __restrict__ clo)
{
    extern __shared__ char smem[];
    const int tid = threadIdx.x, lane = tid & 31, wid = tid >> 5;  // wid = head
    const int b = blockIdx.y, q0 = blockIdx.x * FQ;
    const uint32_t sb = smem_u32(smem);

    auto load_sc = [&](int kt, int stg) {
#pragma unroll
        for (int p = 0; p < 4; p++) {
            int idx = tid + p * 512, r = idx >> 2, c = idx & 3;
            int h = r >> 5, q = r & 31;
            long long g = (((long long)(b * H_ + h)) * S_ + q0 + q) * S_ + kt * FK + c * 8;
            cp16(sb + stg * F_STAGE + r * F_SC_ROW + c * 16, sc16 + g);
        }
    };
    auto load_v = [&](int kt, int stg) {
#pragma unroll
        for (int p = 0; p < 8; p++) {
            int idx = tid + p * 512, r = idx >> 3, c = idx & 7;
            int h = r >> 5, k = r & 31;
            long long g = ((long long)(b * S_ + kt * FK + k)) * E_ + h * 64 + c * 8;
            cp16(sb + stg * F_STAGE + F_SC_SZ + r * F_V_ROW + c * 16, v16 + g);
        }
    };

    load_sc(0, 0); load_v(0, 0); cp_commit();
    load_sc(1, 1); load_v(1, 1); cp_commit();

    float acc[2][8][4] = {};
    const int sq = tid >> 4, sk4 = (tid & 15) * 4;

    for (int kt = 0; kt < S_ / FK; kt++) {
        cp_wait1();
        __syncthreads();
        const int stg = kt & 1;
        const uint32_t scb  = sb + stg * F_STAGE;
        const uint32_t vbuf = scb + F_SC_SZ;

        {
            const uint32_t a0 = scb + sq * F_SC_ROW + sk4;
            float s0 = 0.f, s1 = 0.f;
            __half2 e2[H_];
#pragma unroll
            for (int h = 0; h < H_; h++) {
                uint32_t raw;
                asm volatile("ld.shared.b32 %0, [%1];" : "=r"(raw) : "r"(a0 + h * (32 * F_SC_ROW)));
                float2 f = __half22float2(*(__half2*)&raw);
                f.x = exp2f(f.x); f.y = exp2f(f.y);
                s0 += f.x; s1 += f.y;
                e2[h] = __floats2half2_rn(f.x, f.y);
            }
            const float i0 = 1.f / s0, i1 = 1.f / s1;
#pragma unroll
            for (int h = 0; h < H_; h++) {
                float2 g = __half22float2(e2[h]);
                __half2 r = __floats2half2_rn(g.x * i0, g.y * i1);
                asm volatile("st.shared.b32 [%0], %1;" :: "r"(a0 + h * (32 * F_SC_ROW)), "r"(*(uint32_t*)&r));
            }
        }
        __syncthreads();

        const uint32_t pa = scb + wid * (32 * F_SC_ROW);
        const uint32_t va = vbuf + wid * (32 * F_V_ROW);
        uint32_t afr[2][2][4];
#pragma unroll
        for (int m = 0; m < 2; m++)
#pragma unroll
            for (int ks = 0; ks < 2; ks++)
                ldsm4(afr[m][ks], pa + (m * 16 + (lane & 15)) * F_SC_ROW + (lane >> 4) * 16 + ks * 32);
#pragma unroll
        for (int ks = 0; ks < 2; ks++)
#pragma unroll
            for (int nt2 = 0; nt2 < 4; nt2++) {
                uint32_t bf[4];
                ldsm4t(bf, va + (ks * 16 + (lane & 15)) * F_V_ROW + nt2 * 32 + (lane >> 4) * 16);
                mma_f16(acc[0][nt2 * 2],     afr[0][ks], bf);
                mma_f16(acc[0][nt2 * 2 + 1], afr[0][ks], bf + 2);
                mma_f16(acc[1][nt2 * 2],     afr[1][ks], bf);
                mma_f16(acc[1][nt2 * 2 + 1], afr[1][ks], bf + 2);
            }
        __syncthreads();
        if (kt + 2 < S_ / FK) { load_sc(kt + 2, stg); load_v(kt + 2, stg); }
        cp_commit();
    }

    const int col0 = wid * 64 + (lane & 3) * 2;
#pragma unroll
    for (int m = 0; m < 2; m++) {
        const int row = q0 + m * 16 + (lane >> 2);
#pragma unroll
        for (int n = 0; n < 8; n++) {
            const int col = col0 + n * 8;
            float v0 = acc[m][n][0], v1 = acc[m][n][1];
            float v2 = acc[m][n][2], v3 = acc[m][n][3];
            __nv_bfloat16 h0 = __float2bfloat16(v0), h1 = __float2bfloat16(v1);
            __nv_bfloat16 h2 = __float2bfloat16(v2), h3 = __float2bfloat16(v3);
            __nv_bfloat162 hp0; hp0.x = h0; hp0.y = h1;
            __nv_bfloat162 hp1; hp1.x = h2; hp1.y = h3;
            __nv_bfloat162 lp0; lp0.x = __float2bfloat16(v0 - __bfloat162float(h0));
                                lp0.y = __float2bfloat16(v1 - __bfloat162float(h1));
            __nv_bfloat162 lp1; lp1.x = __float2bfloat16(v2 - __bfloat162float(h2));
                                lp1.y = __float2bfloat16(v3 - __bfloat162float(h3));
            long long o0 = ((long long)(b * S_ + row)) * E_ + col;
            long long o1 = ((long long)(b * S_ + row + 8)) * E_ + col;
            *(__nv_bfloat162*)(chi + o0) = hp0;
            *(__nv_bfloat162*)(chi + o1) = hp1;
            *(__nv_bfloat162*)(clo + o0) = lp0;
            *(__nv_bfloat162*)(clo + o1) = lp1;
        }
    }
}

// ---------------- launch ----------------
extern "C" void kernel_launch(void* const* d_in, const int* in_sizes, int n_in,
                              void* d_out, int out_size)
{
    const float* x  = (const float*)d_in[0];
    const float* Wq = (const float*)d_in[1];
    const float* bq = (const float*)d_in[2];
    const float* Wk = (const float*)d_in[3];
    const float* bk = (const float*)d_in[4];
    const float* Wv = (const float*)d_in[5];
    const float* bv = (const float*)d_in[6];
    const float* Wo = (const float*)d_in[7];
    const float* bo = (const float*)d_in[8];
    float* out = (float*)d_out;

    __nv_bfloat16 *xhi, *xlo, *whi, *wlo, *chi, *clo;
    __half *qkv16, *sc16;
    cudaGetSymbolAddress((void**)&xhi, g_xhi);  cudaGetSymbolAddress((void**)&xlo, g_xlo);
    cudaGetSymbolAddress((void**)&whi, g_whi);  cudaGetSymbolAddress((void**)&wlo, g_wlo);
    cudaGetSymbolAddress((void**)&qkv16, g_qkv16);
    cudaGetSymbolAddress((void**)&sc16, g_sc16);
    cudaGetSymbolAddress((void**)&chi, g_chi);  cudaGetSymbolAddress((void**)&clo, g_clo);

    constexpr int SMEM_SPLIT = 2 * (2 * 128 * 80 + 2 * 128 * 80);  // 81920
    cudaFuncSetAttribute(gemm_mma<128, true>, cudaFuncAttributeMaxDynamicSharedMemorySize, SMEM_SPLIT);
    cudaFuncSetAttribute(score_gemm, cudaFuncAttributeMaxDynamicSharedMemorySize, SCR_SMEM);
    cudaFuncSetAttribute(attn_pv, cudaFuncAttributeMaxDynamicSharedMemorySize, F_SMEM);

    const int EE = E_ * E_;
    const long long QKV = (long long)NTOK * E_;
    __half* q16 = qkv16;
    __half* k16 = qkv16 + QKV;
    __half* v16 = qkv16 + 2 * QKV;

    // 1) split fp32 -> bf16 hi/lo
    split_kernel<<<2048, 256>>>(x, xhi, xlo, NTOK * E_);
    split4_kernel<<<dim3(256, 4), 256>>>(Wq, Wk, Wv, Wo, whi, wlo);

    // 2) q,k,v projections fused into one launch
    gemm_mma<128, true><<<dim3(E_ / 128, NTOK / 128, 3), 512, SMEM_SPLIT>>>(
        xhi, xlo, whi, wlo, bq, bk, bv,
        nullptr, qkv16, nullptr, nullptr, E_, E_, E_, E_, 1.f,
        0, 0, 0, (long long)EE, 0, QKV);

    // 3) scores (dedicated streaming kernel)
    score_gemm<<<dim3(S_ / 64, 1, B_ * H_), 256, SCR_SMEM>>>(q16, k16, sc16);

    // 4) fused heads-softmax + PV -> ctx split-bf16
    attn_pv<<<dim3(S_ / FQ, B_), 512, F_SMEM>>>(sc16, v16, chi, clo);

    // 5) output projection -> d_out (fp32)
    gemm_mma<128, true><<<dim3(E_ / 128, NTOK / 128, 1), 512, SMEM_SPLIT>>>(
        chi, clo, whi + 3 * EE, wlo + 3 * EE, bo, nullptr, nullptr,
        out, nullptr, nullptr, nullptr, E_, E_, E_, E_, 1.f, 0, 0, 0, 0, 0, 0);
}

// round 8
// speedup vs baseline: 1.4296x; 1.0110x over previous
#include <cuda_runtime.h>
#include <cuda_bf16.h>
#include <cuda_fp16.h>
#include <cstdint>

#define B_   2
#define S_   2048
#define E_   1024
#define H_   16
#define D_   64
#define NTOK (B_*S_)

static constexpr long long SSLL = (long long)S_ * S_;                 // 4194304
static constexpr long long SCORES_ELEMS = (long long)B_ * H_ * SSLL;  // 134217728

// ---------------- static scratch ----------------
__device__ __nv_bfloat16 g_xhi[NTOK*E_], g_xlo[NTOK*E_];
__device__ __nv_bfloat16 g_whi[4*E_*E_], g_wlo[4*E_*E_];
__device__ __half        g_qkv16[3LL*NTOK*E_];  // q | k | v slices
__device__ __half        g_sc16[SCORES_ELEMS];  // scores*log2e/8 fp16 (exp2 domain)
__device__ __nv_bfloat16 g_chi[NTOK*E_], g_clo[NTOK*E_];

// ---------------- asm helpers ----------------
__device__ __forceinline__ uint32_t smem_u32(const void* p) {
    uint32_t a;
    asm("{ .reg .u64 t; cvta.to.shared.u64 t, %1; cvt.u32.u64 %0, t; }" : "=r"(a) : "l"(p));
    return a;
}
__device__ __forceinline__ void cp16(uint32_t dst, const void* src) {
    asm volatile("cp.async.cg.shared.global [%0], [%1], 16;" :: "r"(dst), "l"(src));
}
__device__ __forceinline__ void cp_commit() { asm volatile("cp.async.commit_group;"); }
__device__ __forceinline__ void cp_wait1()  { asm volatile("cp.async.wait_group 1;"); }
__device__ __forceinline__ void ldsm4(uint32_t* r, uint32_t addr) {
    asm volatile("ldmatrix.sync.aligned.m8n8.x4.shared.b16 {%0,%1,%2,%3}, [%4];"
        : "=r"(r[0]), "=r"(r[1]), "=r"(r[2]), "=r"(r[3]) : "r"(addr));
}
__device__ __forceinline__ void ldsm4t(uint32_t* r, uint32_t addr) {
    asm volatile("ldmatrix.sync.aligned.m8n8.x4.trans.shared.b16 {%0,%1,%2,%3}, [%4];"
        : "=r"(r[0]), "=r"(r[1]), "=r"(r[2]), "=r"(r[3]) : "r"(addr));
}
__device__ __forceinline__ void mma_bf16(float* d, const uint32_t* a, const uint32_t* b) {
    asm volatile("mma.sync.aligned.m16n8k16.row.col.f32.bf16.bf16.f32 "
        "{%0,%1,%2,%3}, {%4,%5,%6,%7}, {%8,%9}, {%0,%1,%2,%3};"
        : "+f"(d[0]), "+f"(d[1]), "+f"(d[2]), "+f"(d[3])
        : "r"(a[0]), "r"(a[1]), "r"(a[2]), "r"(a[3]), "r"(b[0]), "r"(b[1]));
}
__device__ __forceinline__ void mma_f16(float* d, const uint32_t* a, const uint32_t* b) {
    asm volatile("mma.sync.aligned.m16n8k16.row.col.f32.f16.f16.f32 "
        "{%0,%1,%2,%3}, {%4,%5,%6,%7}, {%8,%9}, {%0,%1,%2,%3};"
        : "+f"(d[0]), "+f"(d[1]), "+f"(d[2]), "+f"(d[3])
        : "r"(a[0]), "r"(a[1]), "r"(a[2]), "r"(a[3]), "r"(b[0]), "r"(b[1]));
}

// ---------------- utility kernels ----------------
__global__ void split_kernel(const float* __restrict__ src,
                             __nv_bfloat16* __restrict__ hi,
                             __nv_bfloat16* __restrict__ lo, int n) {
    for (int i = blockIdx.x * 256 + threadIdx.x; i < n; i += gridDim.x * 256) {
        float f = src[i];
        __nv_bfloat16 h = __float2bfloat16(f);
        hi[i] = h;
        lo[i] = __float2bfloat16(f - __bfloat162float(h));
    }
}

__global__ void split4_kernel(const float* __restrict__ w0, const float* __restrict__ w1,
                              const float* __restrict__ w2, const float* __restrict__ w3,
                              __nv_bfloat16* __restrict__ hi, __nv_bfloat16* __restrict__ lo) {
    const int z = blockIdx.y;
    const float* src = (z == 0) ? w0 : (z == 1) ? w1 : (z == 2) ? w2 : w3;
    const int off = z * (E_ * E_);
    for (int i = blockIdx.x * 256 + threadIdx.x; i < E_ * E_; i += gridDim.x * 256) {
        float f = src[i];
        __nv_bfloat16 h = __float2bfloat16(f);
        hi[off + i] = h;
        lo[off + i] = __float2bfloat16(f - __bfloat162float(h));
    }
}

// ---------------- split-bf16 mma GEMM (projections) ----------------
// 512 threads, 16 warps as 4m x 4n; warp tile 32m x 32n; BM=BN=128, BK=32.
template <int BN, bool SPLIT>
__global__ __launch_bounds__(512)
void gemm_mma(const __nv_bfloat16* __restrict__ Ahi, const __nv_bfloat16* __restrict__ Alo,
              const __nv_bfloat16* __restrict__ Bhi, const __nv_bfloat16* __restrict__ Blo,
              const float* __restrict__ bias0, const float* __restrict__ bias1,
              const float* __restrict__ bias2,
              float* __restrict__ Cf, __half* __restrict__ C16,
              __nv_bfloat16* __restrict__ Chi, __nv_bfloat16* __restrict__ Clo,
              int lda, int ldb, int ldc, int K, float scale,
              long long aB, long long aH, long long bB, long long bH,
              long long cB, long long cH)
{
    extern __shared__ char smem[];
    constexpr int ASZ = 128 * 80;
    constexpr int BSZ = BN * 80;
    constexpr int OFF_ALO = ASZ;
    constexpr int OFF_BHI = SPLIT ? 2 * ASZ : ASZ;
    constexpr int OFF_BLO = OFF_BHI + BSZ;
    constexpr int STAGE   = OFF_BHI + (SPLIT ? 2 : 1) * BSZ;

    const int tid  = threadIdx.x;
    const int lane = tid & 31;
    const int wid  = tid >> 5;
    const int wm   = wid & 3;                      // 4 m-warps
    const int wn   = wid >> 2;                     // 4 n-warps
    const int zb = blockIdx.z >> 4, zh = blockIdx.z & 15;
    const uint32_t sb = smem_u32(smem);
    const float* bias = (zh == 1) ? bias1 : ((zh == 2) ? bias2 : bias0);

    const __nv_bfloat16* pAhi = Ahi + zb * aB + zh * aH + (long long)blockIdx.y * 128 * lda;
    const __nv_bfloat16* pAlo = SPLIT ? (Alo + zb * aB + zh * aH + (long long)blockIdx.y * 128 * lda) : nullptr;
    const __nv_bfloat16* pBhi = Bhi + zb * bB + zh * bH + (long long)blockIdx.x * BN * ldb;
    const __nv_bfloat16* pBlo = SPLIT ? (Blo + zb * bB + zh * bH + (long long)blockIdx.x * BN * ldb) : nullptr;

    const int arow = tid >> 2, ac = tid & 3;
    const int brow = tid >> 2, bc = tid & 3;

    auto load_stage = [&](int kb, int stg) {
        uint32_t s0 = sb + stg * STAGE;
        {
            long long g = (long long)arow * lda + kb * 32 + ac * 8;
            uint32_t d = s0 + arow * 80 + ac * 16;
            cp16(d, pAhi + g);
            if (SPLIT) cp16(d + OFF_ALO, pAlo + g);
        }
        if (BN == 128 || tid < BN * 4) {
            long long g = (long long)brow * ldb + kb * 32 + bc * 8;
            uint32_t d = s0 + OFF_BHI + brow * 80 + bc * 16;
            cp16(d, pBhi + g);
            if (SPLIT) cp16(d + (OFF_BLO - OFF_BHI), pBlo + g);
        }
    };

    const int KI = K >> 5;
    load_stage(0, 0); cp_commit();
    load_stage(1, 1); cp_commit();

    float acc[2][4][4] = {};   // [m-tile][n8-tile][4]

    const int a_r0 = wm * 32 + (lane & 15);
    const int a_c  = (lane >> 4) * 16;
    const int b_r  = wn * 32 + (lane & 7) + ((lane >> 4) & 1) * 8;
    const int b_c  = ((lane >> 3) & 1) * 16;

    for (int kb = 0; kb < KI; kb++) {
        cp_wait1();
        __syncthreads();
        const uint32_t s0 = sb + (kb & 1) * STAGE;
#pragma unroll
        for (int ks = 0; ks < 2; ks++) {
            const uint32_t koff = ks * 32;
            uint32_t ah[2][4], bh[2][4];
#pragma unroll
            for (int mt = 0; mt < 2; mt++)
                ldsm4(ah[mt], s0 + (a_r0 + mt * 16) * 80 + a_c + koff);
#pragma unroll
            for (int nt2 = 0; nt2 < 2; nt2++)
                ldsm4(bh[nt2], s0 + OFF_BHI + (b_r + nt2 * 16) * 80 + b_c + koff);
#pragma unroll
            for (int mt = 0; mt < 2; mt++)
#pragma unroll
                for (int nt2 = 0; nt2 < 2; nt2++) {
                    mma_bf16(acc[mt][nt2 * 2],     ah[mt], bh[nt2]);
                    mma_bf16(acc[mt][nt2 * 2 + 1], ah[mt], bh[nt2] + 2);
                }
            if (SPLIT) {
                uint32_t bl[2][4];
#pragma unroll
                for (int nt2 = 0; nt2 < 2; nt2++)
                    ldsm4(bl[nt2], s0 + OFF_BLO + (b_r + nt2 * 16) * 80 + b_c + koff);
#pragma unroll
                for (int mt = 0; mt < 2; mt++)
#pragma unroll
                    for (int nt2 = 0; nt2 < 2; nt2++) {
                        mma_bf16(acc[mt][nt2 * 2],     ah[mt], bl[nt2]);
                        mma_bf16(acc[mt][nt2 * 2 + 1], ah[mt], bl[nt2] + 2);
                    }
                uint32_t al[2][4];
#pragma unroll
                for (int mt = 0; mt < 2; mt++)
                    ldsm4(al[mt], s0 + OFF_ALO + (a_r0 + mt * 16) * 80 + a_c + koff);
#pragma unroll
                for (int mt = 0; mt < 2; mt++)
#pragma unroll
                    for (int nt2 = 0; nt2 < 2; nt2++) {
                        mma_bf16(acc[mt][nt2 * 2],     al[mt], bh[nt2]);
                        mma_bf16(acc[mt][nt2 * 2 + 1], al[mt], bh[nt2] + 2);
                    }
            }
        }
        __syncthreads();
        if (kb + 2 < KI) load_stage(kb + 2, kb & 1);
        cp_commit();
    }

    const long long cb = zb * cB + zh * cH;
#pragma unroll
    for (int mt = 0; mt < 2; mt++) {
        const int mrow = blockIdx.y * 128 + wm * 32 + mt * 16 + (lane >> 2);
#pragma unroll
        for (int nt = 0; nt < 4; nt++) {
            const int col = blockIdx.x * BN + wn * 32 + nt * 8 + (lane & 3) * 2;
            float v0 = acc[mt][nt][0] * scale, v1 = acc[mt][nt][1] * scale;
            float v2 = acc[mt][nt][2] * scale, v3 = acc[mt][nt][3] * scale;
            if (bias) {
                float b0 = __ldg(&bias[col]), b1 = __ldg(&bias[col + 1]);
                v0 += b0; v1 += b1; v2 += b0; v3 += b1;
            }
            if (Cf) {
                *(float2*)(Cf + cb + (long long)mrow * ldc + col)       = make_float2(v0, v1);
                *(float2*)(Cf + cb + (long long)(mrow + 8) * ldc + col) = make_float2(v2, v3);
            } else if (C16) {
                __half2 p0; p0.x = __float2half(v0); p0.y = __float2half(v1);
                __half2 p1; p1.x = __float2half(v2); p1.y = __float2half(v3);
                *(__half2*)(C16 + cb + (long long)mrow * ldc + col)       = p0;
                *(__half2*)(C16 + cb + (long long)(mrow + 8) * ldc + col) = p1;
            } else {
                __nv_bfloat16 h0 = __float2bfloat16(v0), h1 = __float2bfloat16(v1);
                __nv_bfloat16 h2 = __float2bfloat16(v2), h3 = __float2bfloat16(v3);
                __nv_bfloat162 hp0; hp0.x = h0; hp0.y = h1;
                __nv_bfloat162 hp1; hp1.x = h2; hp1.y = h3;
                __nv_bfloat162 lp0; lp0.x = __float2bfloat16(v0 - __bfloat162float(h0));
                                    lp0.y = __float2bfloat16(v1 - __bfloat162float(h1));
                __nv_bfloat162 lp1; lp1.x = __float2bfloat16(v2 - __bfloat162float(h2));
                                    lp1.y = __float2bfloat16(v3 - __bfloat162float(h3));
                *(__nv_bfloat162*)(Chi + cb + (long long)mrow * ldc + col)       = hp0;
                *(__nv_bfloat162*)(Chi + cb + (long long)(mrow + 8) * ldc + col) = hp1;
                *(__nv_bfloat162*)(Clo + cb + (long long)mrow * ldc + col)       = lp0;
                *(__nv_bfloat162*)(Clo + cb + (long long)(mrow + 8) * ldc + col) = lp1;
            }
        }
    }
}

// ---------------- dedicated scores kernel ----------------
// 256 threads, 8 warps as 2m x 4n; warp tile 32m x 32n; block 64q x 128k.
#define SCR_AROW 144
#define SCR_ASZ  (64*SCR_AROW)          // 9216
#define SCR_BSZ  (128*SCR_AROW)         // 18432
#define SCR_SMEM (SCR_ASZ + 2*SCR_BSZ)  // 46080

__global__ __launch_bounds__(256, 2)
void score_gemm(const __half* __restrict__ q16, const __half* __restrict__ k16,
                __half* __restrict__ sc16)
{
    extern __shared__ char smem[];
    const int tid = threadIdx.x, lane = tid & 31, wid = tid >> 5;
    const int wm = wid & 1, wn = wid >> 1;      // 2 m-warps x 4 n-warps
    const int bz = blockIdx.z;                  // b*16+h
    const int b = bz >> 4, h = bz & 15;
    const int q0 = blockIdx.x * 64;
    const uint32_t sb = smem_u32(smem);
    const uint32_t sbB = sb + SCR_ASZ;
    const float scale = 0.125f * 1.4426950408889634f;

    const __half* qp = q16 + ((long long)b * S_ + q0) * E_ + h * 64;
    const __half* kp = k16 + (long long)b * S_ * E_ + h * 64;

    auto load_a = [&]() {
#pragma unroll
        for (int p = 0; p < 2; p++) {
            int idx = tid + p * 256, r = idx >> 3, c = idx & 7;
            cp16(sb + r * SCR_AROW + c * 16, qp + (long long)r * E_ + c * 8);
        }
    };
    auto load_b = [&](int kt, int stg) {
        const __half* base = kp + (long long)kt * 128 * E_;
#pragma unroll
        for (int p = 0; p < 4; p++) {
            int idx = tid + p * 256, r = idx >> 3, c = idx & 7;
            cp16(sbB + stg * SCR_BSZ + r * SCR_AROW + c * 16, base + (long long)r * E_ + c * 8);
        }
    };

    load_a(); load_b(0, 0); cp_commit();
    load_b(1, 1); cp_commit();

    const int a_r0 = wm * 32 + (lane & 15);
    const int a_c  = (lane >> 4) * 16;
    const int b_r  = wn * 32 + (lane & 7) + ((lane >> 4) & 1) * 8;
    const int b_c  = ((lane >> 3) & 1) * 16;

    uint32_t afr[2][4][4];   // [m-tile][ks][4] hoisted q fragments
    const int col0 = wn * 32 + (lane & 3) * 2;

    for (int kt = 0; kt < S_ / 128; kt++) {
        cp_wait1();
        __syncthreads();
        if (kt == 0) {
#pragma unroll
            for (int mt = 0; mt < 2; mt++)
#pragma unroll
                for (int ks = 0; ks < 4; ks++)
                    ldsm4(afr[mt][ks], sb + (a_r0 + mt * 16) * SCR_AROW + a_c + ks * 32);
        }
        const uint32_t s0 = sbB + (kt & 1) * SCR_BSZ;
        float acc[2][4][4] = {};
#pragma unroll
        for (int ks = 0; ks < 4; ks++) {
#pragma unroll
            for (int nt2 = 0; nt2 < 2; nt2++) {
                uint32_t bf[4];
                ldsm4(bf, s0 + (b_r + nt2 * 16) * SCR_AROW + b_c + ks * 32);
#pragma unroll
                for (int mt = 0; mt < 2; mt++) {
                    mma_f16(acc[mt][nt2 * 2],     afr[mt][ks], bf);
                    mma_f16(acc[mt][nt2 * 2 + 1], afr[mt][ks], bf + 2);
                }
            }
        }
        __syncthreads();
        if (kt + 2 < S_ / 128) load_b(kt + 2, kt & 1);
        cp_commit();

        // write this 64x128 fp16 tile
#pragma unroll
        for (int mt = 0; mt < 2; mt++) {
            const int mrow = q0 + wm * 32 + mt * 16 + (lane >> 2);
            const long long ob = ((long long)bz * S_ + mrow) * S_ + kt * 128;
#pragma unroll
            for (int nt = 0; nt < 4; nt++) {
                const int col = col0 + nt * 8;
                __half2 p0; p0.x = __float2half(acc[mt][nt][0] * scale); p0.y = __float2half(acc[mt][nt][1] * scale);
                __half2 p1; p1.x = __float2half(acc[mt][nt][2] * scale); p1.y = __float2half(acc[mt][nt][3] * scale);
                *(__half2*)(sc16 + ob + col)            = p0;
                *(__half2*)(sc16 + ob + 8LL * S_ + col) = p1;
            }
        }
    }
}

// ---------------- fused heads-softmax + PV ----------------
#define FQ 32
#define FK 32
#define F_SC_ROW 80
#define F_V_ROW  144
#define F_SC_SZ  (512*F_SC_ROW)        // 40960
#define F_V_SZ   (512*F_V_ROW)         // 73728
#define F_STAGE  (F_SC_SZ + F_V_SZ)    // 114688
#define F_SMEM   (2*F_STAGE)           // 229376

__global__ __launch_bounds__(512, 1)
void attn_pv(const __half* __restrict__ sc16, const __half* __restrict__ v16,
             __nv_bfloat16* __restrict__ chi, __nv_bfloat16* __restrict__ clo)
{
    extern __shared__ char smem[];
    const int tid = threadIdx.x, lane = tid & 31, wid = tid >> 5;  // wid = head
    const int b = blockIdx.y, q0 = blockIdx.x * FQ;
    const uint32_t sb = smem_u32(smem);

    auto load_sc = [&](int kt, int stg) {
#pragma unroll
        for (int p = 0; p < 4; p++) {
            int idx = tid + p * 512, r = idx >> 2, c = idx & 3;
            int h = r >> 5, q = r & 31;
            long long g = (((long long)(b * H_ + h)) * S_ + q0 + q) * S_ + kt * FK + c * 8;
            cp16(sb + stg * F_STAGE + r * F_SC_ROW + c * 16, sc16 + g);
        }
    };
    auto load_v = [&](int kt, int stg) {
#pragma unroll
        for (int p = 0; p < 8; p++) {
            int idx = tid + p * 512, r = idx >> 3, c = idx & 7;
            int h = r >> 5, k = r & 31;
            long long g = ((long long)(b * S_ + kt * FK + k)) * E_ + h * 64 + c * 8;
            cp16(sb + stg * F_STAGE + F_SC_SZ + r * F_V_ROW + c * 16, v16 + g);
        }
    };

    load_sc(0, 0); load_v(0, 0); cp_commit();
    load_sc(1, 1); load_v(1, 1); cp_commit();

    float acc[2][8][4] = {};
    const int sq = tid >> 3, sk8 = (tid & 7) * 8;   // 256 threads: (q, 4-k group)

    for (int kt = 0; kt < S_ / FK; kt++) {
        cp_wait1();
        __syncthreads();
        const int stg = kt & 1;
        const uint32_t scb  = sb + stg * F_STAGE;
        const uint32_t vbuf = scb + F_SC_SZ;

        // heads-softmax: 256 active threads, 4 k's each via b64 smem accesses
        if (tid < 256) {
            const uint32_t a0 = scb + sq * F_SC_ROW + sk8;
            float s0 = 0.f, s1 = 0.f, s2 = 0.f, s3 = 0.f;
            uint32_t e0[H_], e1[H_];
#pragma unroll
            for (int h = 0; h < H_; h++) {
                uint32_t r0, r1;
                asm volatile("ld.shared.v2.b32 {%0, %1}, [%2];"
                    : "=r"(r0), "=r"(r1) : "r"(a0 + h * (32 * F_SC_ROW)));
                float2 f0 = __half22float2(*(__half2*)&r0);
                float2 f1 = __half22float2(*(__half2*)&r1);
                f0.x = exp2f(f0.x); f0.y = exp2f(f0.y);
                f1.x = exp2f(f1.x); f1.y = exp2f(f1.y);
                s0 += f0.x; s1 += f0.y; s2 += f1.x; s3 += f1.y;
                __half2 h0 = __floats2half2_rn(f0.x, f0.y);
                __half2 h1 = __floats2half2_rn(f1.x, f1.y);
                e0[h] = *(uint32_t*)&h0; e1[h] = *(uint32_t*)&h1;
            }
            const float i0 = 1.f / s0, i1 = 1.f / s1, i2 = 1.f / s2, i3 = 1.f / s3;
#pragma unroll
            for (int h = 0; h < H_; h++) {
                float2 f0 = __half22float2(*(__half2*)&e0[h]);
                float2 f1 = __half22float2(*(__half2*)&e1[h]);
                __half2 r0 = __floats2half2_rn(f0.x * i0, f0.y * i1);
                __half2 r1 = __floats2half2_rn(f1.x * i2, f1.y * i3);
                asm volatile("st.shared.v2.b32 [%0], {%1, %2};"
                    :: "r"(a0 + h * (32 * F_SC_ROW)), "r"(*(uint32_t*)&r0), "r"(*(uint32_t*)&r1));
            }
        }
        __syncthreads();

        const uint32_t pa = scb + wid * (32 * F_SC_ROW);
        const uint32_t va = vbuf + wid * (32 * F_V_ROW);
        uint32_t afr[2][2][4];
#pragma unroll
        for (int m = 0; m < 2; m++)
#pragma unroll
            for (int ks = 0; ks < 2; ks++)
                ldsm4(afr[m][ks], pa + (m * 16 + (lane & 15)) * F_SC_ROW + (lane >> 4) * 16 + ks * 32);
#pragma unroll
        for (int ks = 0; ks < 2; ks++)
#pragma unroll
            for (int nt2 = 0; nt2 < 4; nt2++) {
                uint32_t bf[4];
                ldsm4t(bf, va + (ks * 16 + (lane & 15)) * F_V_ROW + nt2 * 32 + (lane >> 4) * 16);
                mma_f16(acc[0][nt2 * 2],     afr[0][ks], bf);
                mma_f16(acc[0][nt2 * 2 + 1], afr[0][ks], bf + 2);
                mma_f16(acc[1][nt2 * 2],     afr[1][ks], bf);
                mma_f16(acc[1][nt2 * 2 + 1], afr[1][ks], bf + 2);
            }
        __syncthreads();
        if (kt + 2 < S_ / FK) { load_sc(kt + 2, stg); load_v(kt + 2, stg); }
        cp_commit();
    }

    const int col0 = wid * 64 + (lane & 3) * 2;
#pragma unroll
    for (int m = 0; m < 2; m++) {
        const int row = q0 + m * 16 + (lane >> 2);
#pragma unroll
        for (int n = 0; n < 8; n++) {
            const int col = col0 + n * 8;
            float v0 = acc[m][n][0], v1 = acc[m][n][1];
            float v2 = acc[m][n][2], v3 = acc[m][n][3];
            __nv_bfloat16 h0 = __float2bfloat16(v0), h1 = __float2bfloat16(v1);
            __nv_bfloat16 h2 = __float2bfloat16(v2), h3 = __float2bfloat16(v3);
            __nv_bfloat162 hp0; hp0.x = h0; hp0.y = h1;
            __nv_bfloat162 hp1; hp1.x = h2; hp1.y = h3;
            __nv_bfloat162 lp0; lp0.x = __float2bfloat16(v0 - __bfloat162float(h0));
                                lp0.y = __float2bfloat16(v1 - __bfloat162float(h1));
            __nv_bfloat162 lp1; lp1.x = __float2bfloat16(v2 - __bfloat162float(h2));
                                lp1.y = __float2bfloat16(v3 - __bfloat162float(h3));
            long long o0 = ((long long)(b * S_ + row)) * E_ + col;
            long long o1 = ((long long)(b * S_ + row + 8)) * E_ + col;
            *(__nv_bfloat162*)(chi + o0) = hp0;
            *(__nv_bfloat162*)(chi + o1) = hp1;
            *(__nv_bfloat162*)(clo + o0) = lp0;
            *(__nv_bfloat162*)(clo + o1) = lp1;
        }
    }
}

// ---------------- launch ----------------
extern "C" void kernel_launch(void* const* d_in, const int* in_sizes, int n_in,
                              void* d_out, int out_size)
{
    const float* x  = (const float*)d_in[0];
    const float* Wq = (const float*)d_in[1];
    const float* bq = (const float*)d_in[2];
    const float* Wk = (const float*)d_in[3];
    const float* bk = (const float*)d_in[4];
    const float* Wv = (const float*)d_in[5];
    const float* bv = (const float*)d_in[6];
    const float* Wo = (const float*)d_in[7];
    const float* bo = (const float*)d_in[8];
    float* out = (float*)d_out;

    __nv_bfloat16 *xhi, *xlo, *whi, *wlo, *chi, *clo;
    __half *qkv16, *sc16;
    cudaGetSymbolAddress((void**)&xhi, g_xhi);  cudaGetSymbolAddress((void**)&xlo, g_xlo);
    cudaGetSymbolAddress((void**)&whi, g_whi);  cudaGetSymbolAddress((void**)&wlo, g_wlo);
    cudaGetSymbolAddress((void**)&qkv16, g_qkv16);
    cudaGetSymbolAddress((void**)&sc16, g_sc16);
    cudaGetSymbolAddress((void**)&chi, g_chi);  cudaGetSymbolAddress((void**)&clo, g_clo);

    constexpr int SMEM_SPLIT = 2 * (2 * 128 * 80 + 2 * 128 * 80);  // 81920
    cudaFuncSetAttribute(gemm_mma<128, true>, cudaFuncAttributeMaxDynamicSharedMemorySize, SMEM_SPLIT);
    cudaFuncSetAttribute(score_gemm, cudaFuncAttributeMaxDynamicSharedMemorySize, SCR_SMEM);
    cudaFuncSetAttribute(attn_pv, cudaFuncAttributeMaxDynamicSharedMemorySize, F_SMEM);

    const int EE = E_ * E_;
    const long long QKV = (long long)NTOK * E_;
    __half* q16 = qkv16;
    __half* k16 = qkv16 + QKV;
    __half* v16 = qkv16 + 2 * QKV;

    // 1) split fp32 -> bf16 hi/lo
    split_kernel<<<2048, 256>>>(x, xhi, xlo, NTOK * E_);
    split4_kernel<<<dim3(256, 4), 256>>>(Wq, Wk, Wv, Wo, whi, wlo);

    // 2) q,k,v projections fused into one launch
    gemm_mma<128, true><<<dim3(E_ / 128, NTOK / 128, 3), 512, SMEM_SPLIT>>>(
        xhi, xlo, whi, wlo, bq, bk, bv,
        nullptr, qkv16, nullptr, nullptr, E_, E_, E_, E_, 1.f,
        0, 0, 0, (long long)EE, 0, QKV);

    // 3) scores (dedicated streaming kernel)
    score_gemm<<<dim3(S_ / 64, 1, B_ * H_), 256, SCR_SMEM>>>(q16, k16, sc16);

    // 4) fused heads-softmax + PV -> ctx split-bf16
    attn_pv<<<dim3(S_ / FQ, B_), 512, F_SMEM>>>(sc16, v16, chi, clo);

    // 5) output projection -> d_out (fp32)
    gemm_mma<128, true><<<dim3(E_ / 128, NTOK / 128, 1), 512, SMEM_SPLIT>>>(
        chi, clo, whi + 3 * EE, wlo + 3 * EE, bo, nullptr, nullptr,
        out, nullptr, nullptr, nullptr, E_, E_, E_, E_, 1.f, 0, 0, 0, 0, 0, 0);
}

// round 9
// speedup vs baseline: 1.5170x; 1.0611x over previous
#include <cuda_runtime.h>
#include <cuda_bf16.h>
#include <cuda_fp16.h>
#include <cstdint>

#define B_   2
#define S_   2048
#define E_   1024
#define H_   16
#define D_   64
#define NTOK (B_*S_)

// ---------------- static scratch ----------------
__device__ __nv_bfloat16 g_xhi[NTOK*E_], g_xlo[NTOK*E_];
__device__ __nv_bfloat16 g_whi[4*E_*E_], g_wlo[4*E_*E_];
__device__ __half        g_qkv16[3LL*NTOK*E_];  // q | k | v slices
__device__ __nv_bfloat16 g_chi[NTOK*E_], g_clo[NTOK*E_];

// ---------------- asm helpers ----------------
__device__ __forceinline__ uint32_t smem_u32(const void* p) {
    uint32_t a;
    asm("{ .reg .u64 t; cvta.to.shared.u64 t, %1; cvt.u32.u64 %0, t; }" : "=r"(a) : "l"(p));
    return a;
}
__device__ __forceinline__ void cp16(uint32_t dst, const void* src) {
    asm volatile("cp.async.cg.shared.global [%0], [%1], 16;" :: "r"(dst), "l"(src));
}
__device__ __forceinline__ void cp_commit() { asm volatile("cp.async.commit_group;"); }
__device__ __forceinline__ void cp_wait1()  { asm volatile("cp.async.wait_group 1;"); }
__device__ __forceinline__ void cp_wait0()  { asm volatile("cp.async.wait_group 0;"); }
__device__ __forceinline__ void ldsm4(uint32_t* r, uint32_t addr) {
    asm volatile("ldmatrix.sync.aligned.m8n8.x4.shared.b16 {%0,%1,%2,%3}, [%4];"
        : "=r"(r[0]), "=r"(r[1]), "=r"(r[2]), "=r"(r[3]) : "r"(addr));
}
__device__ __forceinline__ void ldsm4t(uint32_t* r, uint32_t addr) {
    asm volatile("ldmatrix.sync.aligned.m8n8.x4.trans.shared.b16 {%0,%1,%2,%3}, [%4];"
        : "=r"(r[0]), "=r"(r[1]), "=r"(r[2]), "=r"(r[3]) : "r"(addr));
}
__device__ __forceinline__ void mma_bf16(float* d, const uint32_t* a, const uint32_t* b) {
    asm volatile("mma.sync.aligned.m16n8k16.row.col.f32.bf16.bf16.f32 "
        "{%0,%1,%2,%3}, {%4,%5,%6,%7}, {%8,%9}, {%0,%1,%2,%3};"
        : "+f"(d[0]), "+f"(d[1]), "+f"(d[2]), "+f"(d[3])
        : "r"(a[0]), "r"(a[1]), "r"(a[2]), "r"(a[3]), "r"(b[0]), "r"(b[1]));
}
__device__ __forceinline__ void mma_f16(float* d, const uint32_t* a, const uint32_t* b) {
    asm volatile("mma.sync.aligned.m16n8k16.row.col.f32.f16.f16.f32 "
        "{%0,%1,%2,%3}, {%4,%5,%6,%7}, {%8,%9}, {%0,%1,%2,%3};"
        : "+f"(d[0]), "+f"(d[1]), "+f"(d[2]), "+f"(d[3])
        : "r"(a[0]), "r"(a[1]), "r"(a[2]), "r"(a[3]), "r"(b[0]), "r"(b[1]));
}

// ---------------- utility kernels ----------------
__global__ void split_kernel(const float* __restrict__ src,
                             __nv_bfloat16* __restrict__ hi,
                             __nv_bfloat16* __restrict__ lo, int n) {
    for (int i = blockIdx.x * 256 + threadIdx.x; i < n; i += gridDim.x * 256) {
        float f = src[i];
        __nv_bfloat16 h = __float2bfloat16(f);
        hi[i] = h;
        lo[i] = __float2bfloat16(f - __bfloat162float(h));
    }
}

__global__ void split4_kernel(const float* __restrict__ w0, const float* __restrict__ w1,
                              const float* __restrict__ w2, const float* __restrict__ w3,
                              __nv_bfloat16* __restrict__ hi, __nv_bfloat16* __restrict__ lo) {
    const int z = blockIdx.y;
    const float* src = (z == 0) ? w0 : (z == 1) ? w1 : (z == 2) ? w2 : w3;
    const int off = z * (E_ * E_);
    for (int i = blockIdx.x * 256 + threadIdx.x; i < E_ * E_; i += gridDim.x * 256) {
        float f = src[i];
        __nv_bfloat16 h = __float2bfloat16(f);
        hi[off + i] = h;
        lo[off + i] = __float2bfloat16(f - __bfloat162float(h));
    }
}

// ---------------- split-bf16 mma GEMM (projections) ----------------
// 512 threads, 16 warps as 4m x 4n; warp tile 32m x 32n; BM=BN=128, BK=32.
template <int BN, bool SPLIT>
__global__ __launch_bounds__(512)
void gemm_mma(const __nv_bfloat16* __restrict__ Ahi, const __nv_bfloat16* __restrict__ Alo,
              const __nv_bfloat16* __restrict__ Bhi, const __nv_bfloat16* __restrict__ Blo,
              const float* __restrict__ bias0, const float* __restrict__ bias1,
              const float* __restrict__ bias2,
              float* __restrict__ Cf, __half* __restrict__ C16,
              __nv_bfloat16* __restrict__ Chi, __nv_bfloat16* __restrict__ Clo,
              int lda, int ldb, int ldc, int K, float scale,
              long long aB, long long aH, long long bB, long long bH,
              long long cB, long long cH)
{
    extern __shared__ char smem[];
    constexpr int ASZ = 128 * 80;
    constexpr int BSZ = BN * 80;
    constexpr int OFF_ALO = ASZ;
    constexpr int OFF_BHI = SPLIT ? 2 * ASZ : ASZ;
    constexpr int OFF_BLO = OFF_BHI + BSZ;
    constexpr int STAGE   = OFF_BHI + (SPLIT ? 2 : 1) * BSZ;

    const int tid  = threadIdx.x;
    const int lane = tid & 31;
    const int wid  = tid >> 5;
    const int wm   = wid & 3;
    const int wn   = wid >> 2;
    const int zb = blockIdx.z >> 4, zh = blockIdx.z & 15;
    const uint32_t sb = smem_u32(smem);
    const float* bias = (zh == 1) ? bias1 : ((zh == 2) ? bias2 : bias0);

    const __nv_bfloat16* pAhi = Ahi + zb * aB + zh * aH + (long long)blockIdx.y * 128 * lda;
    const __nv_bfloat16* pAlo = SPLIT ? (Alo + zb * aB + zh * aH + (long long)blockIdx.y * 128 * lda) : nullptr;
    const __nv_bfloat16* pBhi = Bhi + zb * bB + zh * bH + (long long)blockIdx.x * BN * ldb;
    const __nv_bfloat16* pBlo = SPLIT ? (Blo + zb * bB + zh * bH + (long long)blockIdx.x * BN * ldb) : nullptr;

    const int arow = tid >> 2, ac = tid & 3;
    const int brow = tid >> 2, bc = tid & 3;

    auto load_stage = [&](int kb, int stg) {
        uint32_t s0 = sb + stg * STAGE;
        {
            long long g = (long long)arow * lda + kb * 32 + ac * 8;
            uint32_t d = s0 + arow * 80 + ac * 16;
            cp16(d, pAhi + g);
            if (SPLIT) cp16(d + OFF_ALO, pAlo + g);
        }
        if (BN == 128 || tid < BN * 4) {
            long long g = (long long)brow * ldb + kb * 32 + bc * 8;
            uint32_t d = s0 + OFF_BHI + brow * 80 + bc * 16;
            cp16(d, pBhi + g);
            if (SPLIT) cp16(d + (OFF_BLO - OFF_BHI), pBlo + g);
        }
    };

    const int KI = K >> 5;
    load_stage(0, 0); cp_commit();
    load_stage(1, 1); cp_commit();

    float acc[2][4][4] = {};

    const int a_r0 = wm * 32 + (lane & 15);
    const int a_c  = (lane >> 4) * 16;
    const int b_r  = wn * 32 + (lane & 7) + ((lane >> 4) & 1) * 8;
    const int b_c  = ((lane >> 3) & 1) * 16;

    for (int kb = 0; kb < KI; kb++) {
        cp_wait1();
        __syncthreads();
        const uint32_t s0 = sb + (kb & 1) * STAGE;
#pragma unroll
        for (int ks = 0; ks < 2; ks++) {
            const uint32_t koff = ks * 32;
            uint32_t ah[2][4], bh[2][4];
#pragma unroll
            for (int mt = 0; mt < 2; mt++)
                ldsm4(ah[mt], s0 + (a_r0 + mt * 16) * 80 + a_c + koff);
#pragma unroll
            for (int nt2 = 0; nt2 < 2; nt2++)
                ldsm4(bh[nt2], s0 + OFF_BHI + (b_r + nt2 * 16) * 80 + b_c + koff);
#pragma unroll
            for (int mt = 0; mt < 2; mt++)
#pragma unroll
                for (int nt2 = 0; nt2 < 2; nt2++) {
                    mma_bf16(acc[mt][nt2 * 2],     ah[mt], bh[nt2]);
                    mma_bf16(acc[mt][nt2 * 2 + 1], ah[mt], bh[nt2] + 2);
                }
            if (SPLIT) {
                uint32_t bl[2][4];
#pragma unroll
                for (int nt2 = 0; nt2 < 2; nt2++)
                    ldsm4(bl[nt2], s0 + OFF_BLO + (b_r + nt2 * 16) * 80 + b_c + koff);
#pragma unroll
                for (int mt = 0; mt < 2; mt++)
#pragma unroll
                    for (int nt2 = 0; nt2 < 2; nt2++) {
                        mma_bf16(acc[mt][nt2 * 2],     ah[mt], bl[nt2]);
                        mma_bf16(acc[mt][nt2 * 2 + 1], ah[mt], bl[nt2] + 2);
                    }
                uint32_t al[2][4];
#pragma unroll
                for (int mt = 0; mt < 2; mt++)
                    ldsm4(al[mt], s0 + OFF_ALO + (a_r0 + mt * 16) * 80 + a_c + koff);
#pragma unroll
                for (int mt = 0; mt < 2; mt++)
#pragma unroll
                    for (int nt2 = 0; nt2 < 2; nt2++) {
                        mma_bf16(acc[mt][nt2 * 2],     al[mt], bh[nt2]);
                        mma_bf16(acc[mt][nt2 * 2 + 1], al[mt], bh[nt2] + 2);
                    }
            }
        }
        __syncthreads();
        if (kb + 2 < KI) load_stage(kb + 2, kb & 1);
        cp_commit();
    }

    const long long cb = zb * cB + zh * cH;
#pragma unroll
    for (int mt = 0; mt < 2; mt++) {
        const int mrow = blockIdx.y * 128 + wm * 32 + mt * 16 + (lane >> 2);
#pragma unroll
        for (int nt = 0; nt < 4; nt++) {
            const int col = blockIdx.x * BN + wn * 32 + nt * 8 + (lane & 3) * 2;
            float v0 = acc[mt][nt][0] * scale, v1 = acc[mt][nt][1] * scale;
            float v2 = acc[mt][nt][2] * scale, v3 = acc[mt][nt][3] * scale;
            if (bias) {
                float b0 = __ldg(&bias[col]), b1 = __ldg(&bias[col + 1]);
                v0 += b0; v1 += b1; v2 += b0; v3 += b1;
            }
            if (Cf) {
                *(float2*)(Cf + cb + (long long)mrow * ldc + col)       = make_float2(v0, v1);
                *(float2*)(Cf + cb + (long long)(mrow + 8) * ldc + col) = make_float2(v2, v3);
            } else if (C16) {
                __half2 p0; p0.x = __float2half(v0); p0.y = __float2half(v1);
                __half2 p1; p1.x = __float2half(v2); p1.y = __float2half(v3);
                *(__half2*)(C16 + cb + (long long)mrow * ldc + col)       = p0;
                *(__half2*)(C16 + cb + (long long)(mrow + 8) * ldc + col) = p1;
            } else {
                __nv_bfloat16 h0 = __float2bfloat16(v0), h1 = __float2bfloat16(v1);
                __nv_bfloat16 h2 = __float2bfloat16(v2), h3 = __float2bfloat16(v3);
                __nv_bfloat162 hp0; hp0.x = h0; hp0.y = h1;
                __nv_bfloat162 hp1; hp1.x = h2; hp1.y = h3;
                __nv_bfloat162 lp0; lp0.x = __float2bfloat16(v0 - __bfloat162float(h0));
                                    lp0.y = __float2bfloat16(v1 - __bfloat162float(h1));
                __nv_bfloat162 lp1; lp1.x = __float2bfloat16(v2 - __bfloat162float(h2));
                                    lp1.y = __float2bfloat16(v3 - __bfloat162float(h3));
                *(__nv_bfloat162*)(Chi + cb + (long long)mrow * ldc + col)       = hp0;
                *(__nv_bfloat162*)(Chi + cb + (long long)(mrow + 8) * ldc + col) = hp1;
                *(__nv_bfloat162*)(Clo + cb + (long long)mrow * ldc + col)       = lp0;
                *(__nv_bfloat162*)(Clo + cb + (long long)(mrow + 8) * ldc + col) = lp1;
            }
        }
    }
}

// ---------------- fully fused attention: QK^T + heads-softmax + PV ----------------
// Block: (b, 32 queries, all 16 heads); 512 threads, warp = head.
// Streams 128 k-tiles of 16 tokens. No scores materialization.
//  phase 1 (warp=head): QK MMA -> exp2 in registers -> unnormalized probs fp16 to smem
//  phase 2 (cross-warp): denom over 16 heads per (q,k) -> inv matrix (fp16, 32x16)
//  phase 3 (warp=head): probs-frag (x) inv-frag via hmul2 -> PV MMA into fp32 acc
#define AQ 32
#define AK 16
#define KV_ROW 144
#define KV_SZ  (H_*AK*KV_ROW)            // 36864 per tensor per stage
#define P_ROW  48
#define OFF_V  (2*KV_SZ)                 // 73728
#define OFF_P  (4*KV_SZ)                 // 147456
#define OFF_I  (OFF_P + H_*AQ*P_ROW)     // +24576 = 172032
#define ATT_SMEM (OFF_I + AQ*P_ROW)      // +1536  = 173568

__global__ __launch_bounds__(512, 1)
void attn_fused(const __half* __restrict__ q16, const __half* __restrict__ k16,
                const __half* __restrict__ v16,
                __nv_bfloat16* __restrict__ chi, __nv_bfloat16* __restrict__ clo)
{
    extern __shared__ char smem[];
    const int tid = threadIdx.x, lane = tid & 31, wid = tid >> 5;  // wid = head
    const int b = blockIdx.y, q0 = blockIdx.x * AQ;
    const uint32_t sb = smem_u32(smem);
    const float SC = 0.125f * 1.4426950408889634f;   // fold /sqrt(D) and log2e

    // ---- prologue: stage Q tile (rows h*32+q, 144B) into [K0|K1] region, hoist frags
    {
#pragma unroll
        for (int p = 0; p < 8; p++) {
            int idx = tid + p * 512, r = idx >> 3, c = idx & 7;   // r = h*32+q
            long long g = ((long long)(b * S_ + q0 + (r & 31))) * E_ + (r >> 5) * 64 + c * 8;
            cp16(sb + r * KV_ROW + c * 16, q16 + g);
        }
        cp_commit();
    }
    cp_wait0();
    __syncthreads();
    uint32_t qf[2][4][4];
#pragma unroll
    for (int mt = 0; mt < 2; mt++)
#pragma unroll
        for (int ks = 0; ks < 4; ks++)
            ldsm4(qf[mt][ks], sb + (wid * 32 + mt * 16 + (lane & 15)) * KV_ROW
                                 + (lane >> 4) * 16 + ks * 32);
    __syncthreads();   // everyone done reading Q before K overwrites

    // ---- K/V staging (rows h*16+k, 144B)
    auto load_kv = [&](int kt, int stg) {
        const uint32_t d0 = sb + stg * KV_SZ;
#pragma unroll
        for (int p = 0; p < 4; p++) {
            int idx = tid + p * 512, r = idx >> 3, c = idx & 7;   // r = h*16+k
            long long g = ((long long)(b * S_ + kt * AK + (r & 15))) * E_ + (r >> 4) * 64 + c * 8;
            cp16(d0 + r * KV_ROW + c * 16, k16 + g);
            cp16(d0 + OFF_V + r * KV_ROW + c * 16, v16 + g);
        }
    };

    load_kv(0, 0); cp_commit();
    load_kv(1, 1); cp_commit();

    float acc[2][8][4] = {};
    const int dq = tid >> 3, dk2 = tid & 7;   // denom mapping (256 active)

    for (int kt = 0; kt < S_ / AK; kt++) {
        cp_wait1();
        __syncthreads();
        const int stg = kt & 1;
        const uint32_t kbuf = sb + stg * KV_SZ + wid * (AK * KV_ROW);
        const uint32_t vbuf = kbuf + OFF_V;

        // ---- phase 1: QK MMA + exp2 in regs + store unnormalized probs
        {
            float sacc[2][2][4] = {};
            const int b_r = (lane & 7) + ((lane >> 4) & 1) * 8;
            const int b_c = ((lane >> 3) & 1) * 16;
#pragma unroll
            for (int ks = 0; ks < 4; ks++) {
                uint32_t bf[4];
                ldsm4(bf, kbuf + b_r * KV_ROW + b_c + ks * 32);
#pragma unroll
                for (int mt = 0; mt < 2; mt++) {
                    mma_f16(sacc[mt][0], qf[mt][ks], bf);
                    mma_f16(sacc[mt][1], qf[mt][ks], bf + 2);
                }
            }
            const uint32_t pbase = sb + OFF_P + wid * (AQ * P_ROW);
#pragma unroll
            for (int mt = 0; mt < 2; mt++)
#pragma unroll
                for (int n8 = 0; n8 < 2; n8++) {
                    float e0 = exp2f(sacc[mt][n8][0] * SC);
                    float e1 = exp2f(sacc[mt][n8][1] * SC);
                    float e2 = exp2f(sacc[mt][n8][2] * SC);
                    float e3 = exp2f(sacc[mt][n8][3] * SC);
                    __half2 p01 = __floats2half2_rn(e0, e1);
                    __half2 p23 = __floats2half2_rn(e2, e3);
                    const int row = mt * 16 + (lane >> 2);
                    const int col = n8 * 8 + (lane & 3) * 2;
                    asm volatile("st.shared.b32 [%0], %1;"
                        :: "r"(pbase + row * P_ROW + col * 2), "r"(*(uint32_t*)&p01));
                    asm volatile("st.shared.b32 [%0], %1;"
                        :: "r"(pbase + (row + 8) * P_ROW + col * 2), "r"(*(uint32_t*)&p23));
                }
        }
        __syncthreads();

        // ---- phase 2: denominators -> inv (32q x 16k fp16)
        if (tid < 256) {
            const uint32_t a0 = sb + OFF_P + dq * P_ROW + dk2 * 4;
            float s0 = 0.f, s1 = 0.f;
#pragma unroll
            for (int h = 0; h < H_; h++) {
                uint32_t raw;
                asm volatile("ld.shared.b32 %0, [%1];" : "=r"(raw)
                    : "r"(a0 + h * (AQ * P_ROW)));
                float2 f = __half22float2(*(__half2*)&raw);
                s0 += f.x; s1 += f.y;
            }
            __half2 iv = __floats2half2_rn(1.f / s0, 1.f / s1);
            asm volatile("st.shared.b32 [%0], %1;"
                :: "r"(sb + OFF_I + dq * P_ROW + dk2 * 4), "r"(*(uint32_t*)&iv));
        }
        __syncthreads();

        // ---- phase 3: PV with on-the-fly normalization
        {
            const uint32_t pbase = sb + OFF_P + wid * (AQ * P_ROW);
            uint32_t pf[2][4], ivf[2][4];
#pragma unroll
            for (int mt = 0; mt < 2; mt++) {
                ldsm4(pf[mt],  pbase + (mt * 16 + (lane & 15)) * P_ROW + (lane >> 4) * 16);
                ldsm4(ivf[mt], sb + OFF_I + (mt * 16 + (lane & 15)) * P_ROW + (lane >> 4) * 16);
#pragma unroll
                for (int j = 0; j < 4; j++) {
                    __half2 m = __hmul2(*(__half2*)&pf[mt][j], *(__half2*)&ivf[mt][j]);
                    pf[mt][j] = *(uint32_t*)&m;
                }
            }
#pragma unroll
            for (int nt2 = 0; nt2 < 4; nt2++) {
                uint32_t bf[4];
                ldsm4t(bf, vbuf + (lane & 15) * KV_ROW + nt2 * 32 + (lane >> 4) * 16);
                mma_f16(acc[0][nt2 * 2],     pf[0], bf);
                mma_f16(acc[0][nt2 * 2 + 1], pf[0], bf + 2);
                mma_f16(acc[1][nt2 * 2],     pf[1], bf);
                mma_f16(acc[1][nt2 * 2 + 1], pf[1], bf + 2);
            }
        }
        __syncthreads();
        if (kt + 2 < S_ / AK) load_kv(kt + 2, stg);
        cp_commit();
    }

    // ---- epilogue: ctx[b][q][wid*64+d] split-bf16
    const int col0 = wid * 64 + (lane & 3) * 2;
#pragma unroll
    for (int m = 0; m < 2; m++) {
        const int row = q0 + m * 16 + (lane >> 2);
#pragma unroll
        for (int n = 0; n < 8; n++) {
            const int col = col0 + n * 8;
            float v0 = acc[m][n][0], v1 = acc[m][n][1];
            float v2 = acc[m][n][2], v3 = acc[m][n][3];
            __nv_bfloat16 h0 = __float2bfloat16(v0), h1 = __float2bfloat16(v1);
            __nv_bfloat16 h2 = __float2bfloat16(v2), h3 = __float2bfloat16(v3);
            __nv_bfloat162 hp0; hp0.x = h0; hp0.y = h1;
            __nv_bfloat162 hp1; hp1.x = h2; hp1.y = h3;
            __nv_bfloat162 lp0; lp0.x = __float2bfloat16(v0 - __bfloat162float(h0));
                                lp0.y = __float2bfloat16(v1 - __bfloat162float(h1));
            __nv_bfloat162 lp1; lp1.x = __float2bfloat16(v2 - __bfloat162float(h2));
                                lp1.y = __float2bfloat16(v3 - __bfloat162float(h3));
            long long o0 = ((long long)(b * S_ + row)) * E_ + col;
            long long o1 = ((long long)(b * S_ + row + 8)) * E_ + col;
            *(__nv_bfloat162*)(chi + o0) = hp0;
            *(__nv_bfloat162*)(chi + o1) = hp1;
            *(__nv_bfloat162*)(clo + o0) = lp0;
            *(__nv_bfloat162*)(clo + o1) = lp1;
        }
    }
}

// ---------------- launch ----------------
extern "C" void kernel_launch(void* const* d_in, const int* in_sizes, int n_in,
                              void* d_out, int out_size)
{
    const float* x  = (const float*)d_in[0];
    const float* Wq = (const float*)d_in[1];
    const float* bq = (const float*)d_in[2];
    const float* Wk = (const float*)d_in[3];
    const float* bk = (const float*)d_in[4];
    const float* Wv = (const float*)d_in[5];
    const float* bv = (const float*)d_in[6];
    const float* Wo = (const float*)d_in[7];
    const float* bo = (const float*)d_in[8];
    float* out = (float*)d_out;

    __nv_bfloat16 *xhi, *xlo, *whi, *wlo, *chi, *clo;
    __half *qkv16;
    cudaGetSymbolAddress((void**)&xhi, g_xhi);  cudaGetSymbolAddress((void**)&xlo, g_xlo);
    cudaGetSymbolAddress((void**)&whi, g_whi);  cudaGetSymbolAddress((void**)&wlo, g_wlo);
    cudaGetSymbolAddress((void**)&qkv16, g_qkv16);
    cudaGetSymbolAddress((void**)&chi, g_chi);  cudaGetSymbolAddress((void**)&clo, g_clo);

    constexpr int SMEM_SPLIT = 2 * (2 * 128 * 80 + 2 * 128 * 80);  // 81920
    cudaFuncSetAttribute(gemm_mma<128, true>, cudaFuncAttributeMaxDynamicSharedMemorySize, SMEM_SPLIT);
    cudaFuncSetAttribute(attn_fused, cudaFuncAttributeMaxDynamicSharedMemorySize, ATT_SMEM);

    const int EE = E_ * E_;
    const long long QKV = (long long)NTOK * E_;
    __half* q16 = qkv16;
    __half* k16 = qkv16 + QKV;
    __half* v16 = qkv16 + 2 * QKV;

    // 1) split fp32 -> bf16 hi/lo
    split_kernel<<<2048, 256>>>(x, xhi, xlo, NTOK * E_);
    split4_kernel<<<dim3(256, 4), 256>>>(Wq, Wk, Wv, Wo, whi, wlo);

    // 2) q,k,v projections fused into one launch
    gemm_mma<128, true><<<dim3(E_ / 128, NTOK / 128, 3), 512, SMEM_SPLIT>>>(
        xhi, xlo, whi, wlo, bq, bk, bv,
        nullptr, qkv16, nullptr, nullptr, E_, E_, E_, E_, 1.f,
        0, 0, 0, (long long)EE, 0, QKV);

    // 3) fused attention: scores + heads-softmax + PV -> ctx split-bf16
    attn_fused<<<dim3(S_ / AQ, B_), 512, ATT_SMEM>>>(q16, k16, v16, chi, clo);

    // 4) output projection -> d_out (fp32)
    gemm_mma<128, true><<<dim3(E_ / 128, NTOK / 128, 1), 512, SMEM_SPLIT>>>(
        chi, clo, whi + 3 * EE, wlo + 3 * EE, bo, nullptr, nullptr,
        out, nullptr, nullptr, nullptr, E_, E_, E_, E_, 1.f, 0, 0, 0, 0, 0, 0);
}

// round 10
// speedup vs baseline: 2.0070x; 1.3230x over previous
#include <cuda_runtime.h>
#include <cuda_fp16.h>
#include <cstdint>

#define B_   2
#define S_   2048
#define E_   1024
#define H_   16
#define D_   64
#define NTOK (B_*S_)

// ---------------- static scratch ----------------
__device__ __half g_x16 [NTOK*E_];
__device__ __half g_wh16[4*E_*E_], g_wl16[4*E_*E_];
__device__ __half g_qkv16[3LL*NTOK*E_];  // q | k | v
__device__ __half g_ctx16[NTOK*E_];

// ---------------- asm helpers ----------------
__device__ __forceinline__ uint32_t smem_u32(const void* p) {
    uint32_t a;
    asm("{ .reg .u64 t; cvta.to.shared.u64 t, %1; cvt.u32.u64 %0, t; }" : "=r"(a) : "l"(p));
    return a;
}
__device__ __forceinline__ void cp16(uint32_t dst, const void* src) {
    asm volatile("cp.async.cg.shared.global [%0], [%1], 16;" :: "r"(dst), "l"(src));
}
__device__ __forceinline__ void cp_commit() { asm volatile("cp.async.commit_group;"); }
__device__ __forceinline__ void cp_wait1()  { asm volatile("cp.async.wait_group 1;"); }
__device__ __forceinline__ void cp_wait0()  { asm volatile("cp.async.wait_group 0;"); }
__device__ __forceinline__ void ldsm4(uint32_t* r, uint32_t addr) {
    asm volatile("ldmatrix.sync.aligned.m8n8.x4.shared.b16 {%0,%1,%2,%3}, [%4];"
        : "=r"(r[0]), "=r"(r[1]), "=r"(r[2]), "=r"(r[3]) : "r"(addr));
}
__device__ __forceinline__ void ldsm4t(uint32_t* r, uint32_t addr) {
    asm volatile("ldmatrix.sync.aligned.m8n8.x4.trans.shared.b16 {%0,%1,%2,%3}, [%4];"
        : "=r"(r[0]), "=r"(r[1]), "=r"(r[2]), "=r"(r[3]) : "r"(addr));
}
__device__ __forceinline__ void mma_f16(float* d, const uint32_t* a, const uint32_t* b) {
    asm volatile("mma.sync.aligned.m16n8k16.row.col.f32.f16.f16.f32 "
        "{%0,%1,%2,%3}, {%4,%5,%6,%7}, {%8,%9}, {%0,%1,%2,%3};"
        : "+f"(d[0]), "+f"(d[1]), "+f"(d[2]), "+f"(d[3])
        : "r"(a[0]), "r"(a[1]), "r"(a[2]), "r"(a[3]), "r"(b[0]), "r"(b[1]));
}
// SW128 swizzle: row-local chunk xor
__device__ __forceinline__ uint32_t swz16(int row, int chunk) {
    return (uint32_t)(row * 128 + ((chunk ^ (row & 7)) << 4));
}

// ---------------- utility kernels ----------------
__global__ void cvt16_kernel(const float* __restrict__ src, __half* __restrict__ dst, int n) {
    for (int i = blockIdx.x * 256 + threadIdx.x; i < n; i += gridDim.x * 256)
        dst[i] = __float2half(src[i]);
}

// weights -> fp16 hi/lo (lo is the residual; subnormal fp16 is fine)
__global__ void split4_16_kernel(const float* __restrict__ w0, const float* __restrict__ w1,
                                 const float* __restrict__ w2, const float* __restrict__ w3,
                                 __half* __restrict__ hi, __half* __restrict__ lo) {
    const int z = blockIdx.y;
    const float* src = (z == 0) ? w0 : (z == 1) ? w1 : (z == 2) ? w2 : w3;
    const int off = z * (E_ * E_);
    for (int i = blockIdx.x * 256 + threadIdx.x; i < E_ * E_; i += gridDim.x * 256) {
        float f = src[i];
        __half h = __float2half(f);
        hi[off + i] = h;
        lo[off + i] = __float2half(f - __half2float(h));
    }
}

// ---------------- 2-term fp16 GEMM: C = A @ (Bhi+Blo)^T + bias ----------------
// 512 threads, 16 warps 4m x 4n; warp tile 32x32; BM=BN=128, BK=32.
// zh = blockIdx.z selects weight slice / bias / C slice.
template <int BN>
__global__ __launch_bounds__(512)
void gemm_w2(const __half* __restrict__ A,
             const __half* __restrict__ Bhi, const __half* __restrict__ Blo,
             const float* __restrict__ bias0, const float* __restrict__ bias1,
             const float* __restrict__ bias2,
             float* __restrict__ Cf, __half* __restrict__ C16,
             int lda, int ldb, int ldc, int K,
             long long bH, long long cH)
{
    extern __shared__ char smem[];
    constexpr int ASZ = 128 * 80;
    constexpr int OFF_BHI = ASZ;
    constexpr int OFF_BLO = 2 * ASZ;
    constexpr int STAGE   = 3 * ASZ;      // 30720

    const int tid  = threadIdx.x;
    const int lane = tid & 31;
    const int wid  = tid >> 5;
    const int wm   = wid & 3;
    const int wn   = wid >> 2;
    const int zh   = blockIdx.z;
    const uint32_t sb = smem_u32(smem);
    const float* bias = (zh == 1) ? bias1 : ((zh == 2) ? bias2 : bias0);

    const __half* pA   = A + (long long)blockIdx.y * 128 * lda;
    const __half* pBhi = Bhi + zh * bH + (long long)blockIdx.x * BN * ldb;
    const __half* pBlo = Blo + zh * bH + (long long)blockIdx.x * BN * ldb;

    const int r4 = tid >> 2, c4 = tid & 3;

    auto load_stage = [&](int kb, int stg) {
        uint32_t s0 = sb + stg * STAGE;
        cp16(s0 + r4 * 80 + c4 * 16, pA + (long long)r4 * lda + kb * 32 + c4 * 8);
        long long g = (long long)r4 * ldb + kb * 32 + c4 * 8;
        cp16(s0 + OFF_BHI + r4 * 80 + c4 * 16, pBhi + g);
        cp16(s0 + OFF_BLO + r4 * 80 + c4 * 16, pBlo + g);
    };

    const int KI = K >> 5;
    load_stage(0, 0); cp_commit();
    load_stage(1, 1); cp_commit();

    float acc[2][4][4] = {};

    const int a_r0 = wm * 32 + (lane & 15);
    const int a_c  = (lane >> 4) * 16;
    const int b_r  = wn * 32 + (lane & 7) + ((lane >> 4) & 1) * 8;
    const int b_c  = ((lane >> 3) & 1) * 16;

    for (int kb = 0; kb < KI; kb++) {
        cp_wait1();
        __syncthreads();
        const uint32_t s0 = sb + (kb & 1) * STAGE;
#pragma unroll
        for (int ks = 0; ks < 2; ks++) {
            const uint32_t koff = ks * 32;
            uint32_t ah[2][4], bh[2][4], bl[2][4];
#pragma unroll
            for (int mt = 0; mt < 2; mt++)
                ldsm4(ah[mt], s0 + (a_r0 + mt * 16) * 80 + a_c + koff);
#pragma unroll
            for (int nt2 = 0; nt2 < 2; nt2++) {
                ldsm4(bh[nt2], s0 + OFF_BHI + (b_r + nt2 * 16) * 80 + b_c + koff);
                ldsm4(bl[nt2], s0 + OFF_BLO + (b_r + nt2 * 16) * 80 + b_c + koff);
            }
#pragma unroll
            for (int mt = 0; mt < 2; mt++)
#pragma unroll
                for (int nt2 = 0; nt2 < 2; nt2++) {
                    mma_f16(acc[mt][nt2 * 2],     ah[mt], bh[nt2]);
                    mma_f16(acc[mt][nt2 * 2 + 1], ah[mt], bh[nt2] + 2);
                    mma_f16(acc[mt][nt2 * 2],     ah[mt], bl[nt2]);
                    mma_f16(acc[mt][nt2 * 2 + 1], ah[mt], bl[nt2] + 2);
                }
        }
        __syncthreads();
        if (kb + 2 < KI) load_stage(kb + 2, kb & 1);
        cp_commit();
    }

    const long long cb = zh * cH;
#pragma unroll
    for (int mt = 0; mt < 2; mt++) {
        const int mrow = blockIdx.y * 128 + wm * 32 + mt * 16 + (lane >> 2);
#pragma unroll
        for (int nt = 0; nt < 4; nt++) {
            const int col = blockIdx.x * BN + wn * 32 + nt * 8 + (lane & 3) * 2;
            float v0 = acc[mt][nt][0], v1 = acc[mt][nt][1];
            float v2 = acc[mt][nt][2], v3 = acc[mt][nt][3];
            if (bias) {
                float b0 = __ldg(&bias[col]), b1 = __ldg(&bias[col + 1]);
                v0 += b0; v1 += b1; v2 += b0; v3 += b1;
            }
            if (Cf) {
                *(float2*)(Cf + cb + (long long)mrow * ldc + col)       = make_float2(v0, v1);
                *(float2*)(Cf + cb + (long long)(mrow + 8) * ldc + col) = make_float2(v2, v3);
            } else {
                __half2 p0; p0.x = __float2half(v0); p0.y = __float2half(v1);
                __half2 p1; p1.x = __float2half(v2); p1.y = __float2half(v3);
                *(__half2*)(C16 + cb + (long long)mrow * ldc + col)       = p0;
                *(__half2*)(C16 + cb + (long long)(mrow + 8) * ldc + col) = p1;
            }
        }
    }
}

// ---------------- fully fused attention v2 ----------------
// Block: (b, 32 q, 16 heads); warp = head; k-tiles of 32; SW128 swizzled rows.
// K double-buffered, V single (prefetched), probs packed 2 heads / 128B row.
#define AQ 32
#define NIT (S_/32)                 // 64
#define OFF_K1  65536
#define OFF_V   131072
#define OFF_P   196608              // 8 blocks x 32 rows x 128B = 32768
#define OFF_INV 229376              // 32 rows x 80B = 2560
#define ATT_SMEM 231936

__global__ __launch_bounds__(512, 1)
void attn_fused(const __half* __restrict__ q16, const __half* __restrict__ k16,
                const __half* __restrict__ v16, __half* __restrict__ ctx16)
{
    extern __shared__ char smem[];
    const int tid = threadIdx.x, lane = tid & 31, wid = tid >> 5;  // wid = head
    const int b = blockIdx.y, q0 = blockIdx.x * AQ;
    const uint32_t sb = smem_u32(smem);
    const float SC = 0.125f * 1.4426950408889634f;

    // ---- prologue: stage Q (rows h*32+q) into K0 region, hoist fragments
#pragma unroll
    for (int p = 0; p < 8; p++) {
        int idx = tid + p * 512, r = idx >> 3, c = idx & 7;
        long long g = ((long long)(b * S_ + q0 + (r & 31))) * E_ + (r >> 5) * 64 + c * 8;
        cp16(sb + swz16(r, c), q16 + g);
    }
    cp_commit(); cp_wait0();
    __syncthreads();
    uint32_t qf[2][4][4];
#pragma unroll
    for (int mt = 0; mt < 2; mt++)
#pragma unroll
        for (int ks = 0; ks < 4; ks++) {
            int row = wid * 32 + mt * 16 + (lane & 15);
            ldsm4(qf[mt][ks], sb + swz16(row, ks * 2 + (lane >> 4)));
        }
    __syncthreads();

    auto load_k = [&](int kt, int stg) {
        const uint32_t d0 = sb + stg * OFF_K1;
#pragma unroll
        for (int p = 0; p < 8; p++) {
            int idx = tid + p * 512, r = idx >> 3, c = idx & 7;
            long long g = ((long long)(b * S_ + kt * 32 + (r & 31))) * E_ + (r >> 5) * 64 + c * 8;
            cp16(d0 + swz16(r, c), k16 + g);
        }
    };
    auto load_v = [&](int kt) {
        const uint32_t d0 = sb + OFF_V;
#pragma unroll
        for (int p = 0; p < 8; p++) {
            int idx = tid + p * 512, r = idx >> 3, c = idx & 7;
            long long g = ((long long)(b * S_ + kt * 32 + (r & 31))) * E_ + (r >> 5) * 64 + c * 8;
            cp16(d0 + swz16(r, c), v16 + g);
        }
    };

    load_k(0, 0); load_v(0); cp_commit();   // group: K0+V0
    load_k(1, 1); cp_commit();              // group: K1

    float acc[2][8][4] = {};
    const int pq = tid >> 4, pk = (tid & 15) * 2;   // phase-2 mapping

    for (int kt = 0; kt < NIT; kt++) {
        cp_wait1();
        __syncthreads();
        const int stg = kt & 1;
        const uint32_t kslice = sb + stg * OFF_K1 + wid * 32 * 128;
        const uint32_t vslice = sb + OFF_V + wid * 32 * 128;
        const uint32_t pslice = sb + OFF_P + (wid >> 1) * 4096;
        const int pcb = (wid & 1) * 4;    // prob chunk base for this head

        // ---- phase 1: QK MMA + exp2 + store unnormalized probs (per k-half)
#pragma unroll
        for (int kh = 0; kh < 2; kh++) {
            float sacc[2][2][4] = {};
            const int b_r = kh * 16 + (lane & 7) + ((lane >> 4) & 1) * 8;
#pragma unroll
            for (int ks = 0; ks < 4; ks++) {
                uint32_t bf[4];
                ldsm4(bf, kslice + swz16(b_r, ks * 2 + ((lane >> 3) & 1)));
#pragma unroll
                for (int mt = 0; mt < 2; mt++) {
                    mma_f16(sacc[mt][0], qf[mt][ks], bf);
                    mma_f16(sacc[mt][1], qf[mt][ks], bf + 2);
                }
            }
#pragma unroll
            for (int mt = 0; mt < 2; mt++)
#pragma unroll
                for (int n8 = 0; n8 < 2; n8++) {
                    float e0 = exp2f(sacc[mt][n8][0] * SC);
                    float e1 = exp2f(sacc[mt][n8][1] * SC);
                    float e2 = exp2f(sacc[mt][n8][2] * SC);
                    float e3 = exp2f(sacc[mt][n8][3] * SC);
                    __half2 p01 = __floats2half2_rn(e0, e1);
                    __half2 p23 = __floats2half2_rn(e2, e3);
                    const int row = mt * 16 + (lane >> 2);
                    const int chunk = pcb + kh * 2 + n8;
                    const int boff = ((lane & 3) * 2 & 7) * 2;   // (col&7)*2
                    uint32_t a0 = pslice + (uint32_t)(row * 128) + (uint32_t)(((chunk ^ (row & 7)) << 4)) + boff;
                    uint32_t a1 = pslice + (uint32_t)((row + 8) * 128) + (uint32_t)(((chunk ^ ((row + 8) & 7)) << 4)) + boff;
                    asm volatile("st.shared.b32 [%0], %1;" :: "r"(a0), "r"(*(uint32_t*)&p01));
                    asm volatile("st.shared.b32 [%0], %1;" :: "r"(a1), "r"(*(uint32_t*)&p23));
                }
        }
        __syncthreads();

        // ---- phase 2: denominators over 16 heads -> inv (32q x 32k fp16)
        {
            float s0 = 0.f, s1 = 0.f;
#pragma unroll
            for (int h = 0; h < H_; h++) {
                int chunk = (h & 1) * 4 + (pk >> 3);
                uint32_t a = sb + OFF_P + (h >> 1) * 4096 + pq * 128
                           + (uint32_t)((chunk ^ (pq & 7)) << 4) + (pk & 7) * 2;
                uint32_t raw;
                asm volatile("ld.shared.b32 %0, [%1];" : "=r"(raw) : "r"(a));
                float2 f = __half22float2(*(__half2*)&raw);
                s0 += f.x; s1 += f.y;
            }
            __half2 iv = __floats2half2_rn(1.f / s0, 1.f / s1);
            asm volatile("st.shared.b32 [%0], %1;"
                :: "r"(sb + OFF_INV + pq * 80 + pk * 2), "r"(*(uint32_t*)&iv));
        }
        __syncthreads();

        // ---- phase 3: PV with on-the-fly normalization
#pragma unroll
        for (int kh = 0; kh < 2; kh++) {
            uint32_t pf[2][4];
#pragma unroll
            for (int mt = 0; mt < 2; mt++) {
                const int row = mt * 16 + (lane & 15);
                const int chunk = pcb + kh * 2 + (lane >> 4);
                ldsm4(pf[mt], pslice + (uint32_t)(row * 128) + (uint32_t)((chunk ^ (row & 7)) << 4));
                uint32_t ivf[4];
                ldsm4(ivf, sb + OFF_INV + row * 80 + kh * 32 + (lane >> 4) * 16);
#pragma unroll
                for (int j = 0; j < 4; j++) {
                    __half2 m = __hmul2(*(__half2*)&pf[mt][j], *(__half2*)&ivf[j]);
                    pf[mt][j] = *(uint32_t*)&m;
                }
            }
#pragma unroll
            for (int nt2 = 0; nt2 < 4; nt2++) {
                uint32_t bf[4];
                const int row = kh * 16 + (lane & 15);
                ldsm4t(bf, vslice + swz16(row, nt2 * 2 + (lane >> 4)));
                mma_f16(acc[0][nt2 * 2],     pf[0], bf);
                mma_f16(acc[0][nt2 * 2 + 1], pf[0], bf + 2);
                mma_f16(acc[1][nt2 * 2],     pf[1], bf);
                mma_f16(acc[1][nt2 * 2 + 1], pf[1], bf + 2);
            }
        }
        __syncthreads();

        // ---- issue next loads: V_{kt+1} (group), K_{kt+2} (group) — always commit
        if (kt + 1 < NIT) load_v(kt + 1);
        cp_commit();
        if (kt + 2 < NIT) load_k(kt + 2, stg);
        cp_commit();
    }

    // ---- epilogue: ctx[b][q][wid*64+d] fp16
    const int col0 = wid * 64 + (lane & 3) * 2;
#pragma unroll
    for (int m = 0; m < 2; m++) {
        const int row = q0 + m * 16 + (lane >> 2);
#pragma unroll
        for (int n = 0; n < 8; n++) {
            const int col = col0 + n * 8;
            __half2 p0; p0.x = __float2half(acc[m][n][0]); p0.y = __float2half(acc[m][n][1]);
            __half2 p1; p1.x = __float2half(acc[m][n][2]); p1.y = __float2half(acc[m][n][3]);
            *(__half2*)(ctx16 + ((long long)(b * S_ + row)) * E_ + col)     = p0;
            *(__half2*)(ctx16 + ((long long)(b * S_ + row + 8)) * E_ + col) = p1;
        }
    }
}

// ---------------- launch ----------------
extern "C" void kernel_launch(void* const* d_in, const int* in_sizes, int n_in,
                              void* d_out, int out_size)
{
    const float* x  = (const float*)d_in[0];
    const float* Wq = (const float*)d_in[1];
    const float* bq = (const float*)d_in[2];
    const float* Wk = (const float*)d_in[3];
    const float* bk = (const float*)d_in[4];
    const float* Wv = (const float*)d_in[5];
    const float* bv = (const float*)d_in[6];
    const float* Wo = (const float*)d_in[7];
    const float* bo = (const float*)d_in[8];
    float* out = (float*)d_out;

    __half *x16, *wh16, *wl16, *qkv16, *ctx16;
    cudaGetSymbolAddress((void**)&x16,  g_x16);
    cudaGetSymbolAddress((void**)&wh16, g_wh16);
    cudaGetSymbolAddress((void**)&wl16, g_wl16);
    cudaGetSymbolAddress((void**)&qkv16, g_qkv16);
    cudaGetSymbolAddress((void**)&ctx16, g_ctx16);

    constexpr int SMEM_W2 = 2 * 3 * 128 * 80;   // 61440
    cudaFuncSetAttribute(gemm_w2<128>, cudaFuncAttributeMaxDynamicSharedMemorySize, SMEM_W2);
    cudaFuncSetAttribute(attn_fused, cudaFuncAttributeMaxDynamicSharedMemorySize, ATT_SMEM);

    const int EE = E_ * E_;
    const long long QKV = (long long)NTOK * E_;
    __half* q16 = qkv16;
    __half* k16 = qkv16 + QKV;
    __half* v16 = qkv16 + 2 * QKV;

    // 1) convert inputs
    cvt16_kernel<<<2048, 256>>>(x, x16, NTOK * E_);
    split4_16_kernel<<<dim3(256, 4), 256>>>(Wq, Wk, Wv, Wo, wh16, wl16);

    // 2) q,k,v projections (one launch, z selects weight/bias/output)
    gemm_w2<128><<<dim3(E_ / 128, NTOK / 128, 3), 512, SMEM_W2>>>(
        x16, wh16, wl16, bq, bk, bv,
        nullptr, qkv16, E_, E_, E_, E_, (long long)EE, QKV);

    // 3) fused attention: scores + heads-softmax + PV -> ctx fp16
    attn_fused<<<dim3(S_ / AQ, B_), 512, ATT_SMEM>>>(q16, k16, v16, ctx16);

    // 4) output projection -> d_out (fp32)
    gemm_w2<128><<<dim3(E_ / 128, NTOK / 128, 1), 512, SMEM_W2>>>(
        ctx16, wh16 + 3 * EE, wl16 + 3 * EE, bo, nullptr, nullptr,
        out, nullptr, E_, E_, E_, E_, 0, 0);
}